// round 2
// baseline (speedup 1.0000x reference)
#include <cuda_runtime.h>
#include <math.h>

#define BB   256
#define KK   64
#define DD   2048
#define NPTS 50000
#define CC   5000
#define NHID 512
#define HH2  256
#define MM   (BB*KK)   // 16384

// ---------------- scratch (device globals; no allocations allowed) ----------
__device__ float g_clu[(size_t)CC*DD];      // cluster sum -> mean
__device__ float g_cnt[CC];
__device__ float g_G[(size_t)BB*KK*KK];     // raw gram per batch
__device__ float g_Adj[(size_t)BB*KK*KK];   // softmax adjacency
__device__ float g_X[(size_t)MM*DD];        // normalized, centered node feats
__device__ float g_Ytop[(size_t)MM*NHID];
__device__ float g_Ybot[(size_t)MM*NHID];
__device__ float g_X1[(size_t)MM*NHID];
__device__ float g_Ztop[(size_t)MM*HH2];
__device__ float g_Zbot[(size_t)MM*HH2];
__device__ float g_X2[(size_t)MM*HH2];
__device__ float g_Hc[(size_t)MM*HH2];

// ---------------- kernels ---------------------------------------------------

__global__ void k_zero()
{
    size_t total = (size_t)CC*DD + CC;
    for (size_t i = (size_t)blockIdx.x*blockDim.x + threadIdx.x; i < total;
         i += (size_t)gridDim.x*blockDim.x) {
        if (i < (size_t)CC*DD) g_clu[i] = 0.f;
        else                   g_cnt[i - (size_t)CC*DD] = 0.f;
    }
}

// one block per feature row; coalesced atomic adds into the label's row
__global__ void k_segsum(const float* __restrict__ feats,
                         const int* __restrict__ labels)
{
    int row = blockIdx.x;
    int lab = labels[row];
    const float* src = feats + (size_t)row*DD;
    float* dst = g_clu + (size_t)lab*DD;
    #pragma unroll
    for (int j = 0; j < DD/256; j++) {
        int d = threadIdx.x + j*256;
        atomicAdd(&dst[d], src[d]);
    }
}

__global__ void k_count(const int* __restrict__ labels)
{
    int i = blockIdx.x*blockDim.x + threadIdx.x;
    if (i < NPTS) atomicAdd(&g_cnt[labels[i]], 1.0f);
}

// divide by count, compute simm = sum(mean^2) per cluster
__global__ void k_finalize(float* __restrict__ simm_out)
{
    __shared__ float red[256];
    int c = blockIdx.x;
    float inv = 1.0f / fmaxf(g_cnt[c], 1.0f);
    float* rowm = g_clu + (size_t)c*DD;
    float ss = 0.f;
    #pragma unroll
    for (int j = 0; j < DD/256; j++) {
        int d = threadIdx.x + j*256;
        float v = rowm[d] * inv;
        rowm[d] = v;
        ss += v*v;
    }
    red[threadIdx.x] = ss;
    __syncthreads();
    for (int o = 128; o > 0; o >>= 1) {
        if (threadIdx.x < o) red[threadIdx.x] += red[threadIdx.x + o];
        __syncthreads();
    }
    if (threadIdx.x == 0) simm_out[c] = red[0];
}

// per-batch raw gram G = F F^T  (F rows gathered: row0=features[idx], else clu_mean)
__global__ __launch_bounds__(256)
void k_gram(const float* __restrict__ feats,
            const int* __restrict__ labels,
            const int* __restrict__ knn,
            const int* __restrict__ indexes)
{
    __shared__ const float* rowp[KK];
    __shared__ float Fs[KK][129];
    int b = blockIdx.x;
    int t = threadIdx.x;
    if (t < KK) {
        if (t == 0) rowp[0] = feats + (size_t)indexes[b]*DD;
        else        rowp[t] = g_clu + (size_t)labels[knn[b*KK + t]]*DD;
    }
    __syncthreads();

    float acc[4][4];
    #pragma unroll
    for (int i = 0; i < 4; i++)
        #pragma unroll
        for (int j = 0; j < 4; j++) acc[i][j] = 0.f;

    int tx = t & 15, ty = t >> 4;

    for (int d0 = 0; d0 < DD; d0 += 128) {
        for (int idx = t; idx < KK*128; idx += 256) {
            int r = idx >> 7, c = idx & 127;
            Fs[r][c] = rowp[r][d0 + c];
        }
        __syncthreads();
        #pragma unroll 4
        for (int d = 0; d < 128; d++) {
            float a[4], bv[4];
            #pragma unroll
            for (int i = 0; i < 4; i++) a[i]  = Fs[ty*4 + i][d];
            #pragma unroll
            for (int i = 0; i < 4; i++) bv[i] = Fs[tx*4 + i][d];
            #pragma unroll
            for (int i = 0; i < 4; i++)
                #pragma unroll
                for (int j = 0; j < 4; j++)
                    acc[i][j] = fmaf(a[i], bv[j], acc[i][j]);
        }
        __syncthreads();
    }
    float* Gb = g_G + (size_t)b*KK*KK;
    #pragma unroll
    for (int i = 0; i < 4; i++)
        #pragma unroll
        for (int j = 0; j < 4; j++)
            Gb[(ty*4 + i)*KK + (tx*4 + j)] = acc[i][j];
}

// adjacency: A = softmax_j( G[k][j] * exp(all_pred[b][j][1]) )
__global__ void k_buildA(const float* __restrict__ all_pred)
{
    __shared__ float red[KK];
    int b = blockIdx.x / KK;
    int k = blockIdx.x % KK;
    int j = threadIdx.x;
    float v = g_G[(size_t)b*KK*KK + k*KK + j] * expf(all_pred[(b*KK + j)*2 + 1]);
    red[j] = v;
    __syncthreads();
    for (int o = 32; o > 0; o >>= 1) {
        if (j < o) red[j] = fmaxf(red[j], red[j + o]);
        __syncthreads();
    }
    float mx = red[0];
    __syncthreads();
    float e = expf(v - mx);
    red[j] = e;
    __syncthreads();
    for (int o = 32; o > 0; o >>= 1) {
        if (j < o) red[j] += red[j + o];
        __syncthreads();
    }
    g_Adj[(size_t)b*KK*KK + k*KK + j] = e / red[0];
}

// x[b,k,:] = f_k/||f_k|| - f_0/||f_0||   (norms from gram diagonal)
__global__ void k_buildX(const float* __restrict__ feats,
                         const int* __restrict__ labels,
                         const int* __restrict__ knn,
                         const int* __restrict__ indexes)
{
    int b = blockIdx.x / KK;
    int k = blockIdx.x % KK;
    const float* f0 = feats + (size_t)indexes[b]*DD;
    const float* fk = (k == 0) ? f0
                               : g_clu + (size_t)labels[knn[b*KK + k]]*DD;
    const float* Gb = g_G + (size_t)b*KK*KK;
    float invk = rsqrtf(Gb[k*KK + k]);
    float inv0 = rsqrtf(Gb[0]);
    float* xo = g_X + (size_t)(b*KK + k)*DD;
    #pragma unroll
    for (int j = 0; j < DD/256; j++) {
        int d = threadIdx.x + j*256;
        xo[d] = fk[d]*invk - f0[d]*inv0;
    }
}

// classic 128x128x8 SGEMM, 8x8 microtile, row-major. M%128==0, N%128==0, K%8==0.
__global__ __launch_bounds__(256)
void k_sgemm(int M, int Kd, int N,
             const float* __restrict__ A, int lda,
             const float* __restrict__ B, int ldb,
             float* __restrict__ C, int ldc)
{
    __shared__ float As[8][132];
    __shared__ float Bs[8][128];
    const int t  = threadIdx.x;
    const int tx = t & 15, ty = t >> 4;
    const int row0 = blockIdx.y * 128;
    const int col0 = blockIdx.x * 128;

    const int arow = t >> 1;
    const int akk  = (t & 1) << 2;
    const int bkk  = t >> 5;
    const int bcol = (t & 31) << 2;

    const float* Ap = A + (size_t)(row0 + arow)*lda + akk;
    const float* Bp = B + (size_t)bkk*ldb + col0 + bcol;

    float acc[8][8];
    #pragma unroll
    for (int i = 0; i < 8; i++)
        #pragma unroll
        for (int j = 0; j < 8; j++) acc[i][j] = 0.f;

    for (int k0 = 0; k0 < Kd; k0 += 8) {
        float4 av = *(const float4*)Ap;  Ap += 8;
        float4 bv = *(const float4*)Bp;  Bp += (size_t)8*ldb;
        As[akk+0][arow] = av.x;
        As[akk+1][arow] = av.y;
        As[akk+2][arow] = av.z;
        As[akk+3][arow] = av.w;
        *(float4*)&Bs[bkk][bcol] = bv;
        __syncthreads();
        #pragma unroll
        for (int kk = 0; kk < 8; kk++) {
            float4 a0 = *(const float4*)&As[kk][ty*8];
            float4 a1 = *(const float4*)&As[kk][ty*8 + 4];
            float4 b0 = *(const float4*)&Bs[kk][tx*8];
            float4 b1 = *(const float4*)&Bs[kk][tx*8 + 4];
            float af[8] = {a0.x,a0.y,a0.z,a0.w,a1.x,a1.y,a1.z,a1.w};
            float bf[8] = {b0.x,b0.y,b0.z,b0.w,b1.x,b1.y,b1.z,b1.w};
            #pragma unroll
            for (int i = 0; i < 8; i++)
                #pragma unroll
                for (int j = 0; j < 8; j++)
                    acc[i][j] = fmaf(af[i], bf[j], acc[i][j]);
        }
        __syncthreads();
    }
    #pragma unroll
    for (int i = 0; i < 8; i++) {
        size_t r = (size_t)(row0 + ty*8 + i);
        #pragma unroll
        for (int j = 0; j < 8; j += 4) {
            float4 v = {acc[i][j], acc[i][j+1], acc[i][j+2], acc[i][j+3]};
            *(float4*)&C[r*ldc + col0 + tx*8 + j] = v;
        }
    }
}

// out[b,k,c] = relu(Ytop[b,k,c] + sum_j Adj[b,k,j]*Ybot[b,j,c] + bias[c])
__global__ __launch_bounds__(256)
void k_combine(const float* __restrict__ Ytop,
               const float* __restrict__ Ybot,
               const float* __restrict__ bias,
               float* __restrict__ out, int ncols)
{
    __shared__ float As[KK][KK];   // 16KB
    __shared__ float Bs[32][128];  // 16KB
    int b    = blockIdx.y;
    int col0 = blockIdx.x * 128;
    int t = threadIdx.x;
    int tx = t & 15, ty = t >> 4;

    const float* Ab = g_Adj + (size_t)b*KK*KK;
    for (int idx = t; idx < KK*KK; idx += 256)
        As[idx >> 6][idx & 63] = Ab[idx];

    float acc[4][8];
    #pragma unroll
    for (int i = 0; i < 4; i++)
        #pragma unroll
        for (int c = 0; c < 8; c++) acc[i][c] = 0.f;

    for (int jt = 0; jt < KK; jt += 32) {
        __syncthreads();
        #pragma unroll
        for (int i = 0; i < 4; i++) {
            int idx = t + i*256;
            int j = idx >> 5, c4 = idx & 31;
            *(float4*)&Bs[j][c4*4] =
                *(const float4*)&Ybot[((size_t)(b*KK + jt + j))*ncols + col0 + c4*4];
        }
        __syncthreads();
        #pragma unroll 4
        for (int j = 0; j < 32; j++) {
            float a[4];
            #pragma unroll
            for (int i = 0; i < 4; i++) a[i] = As[ty*4 + i][jt + j];
            float4 b0 = *(const float4*)&Bs[j][tx*8];
            float4 b1 = *(const float4*)&Bs[j][tx*8 + 4];
            float bf[8] = {b0.x,b0.y,b0.z,b0.w,b1.x,b1.y,b1.z,b1.w};
            #pragma unroll
            for (int i = 0; i < 4; i++)
                #pragma unroll
                for (int c = 0; c < 8; c++)
                    acc[i][c] = fmaf(a[i], bf[c], acc[i][c]);
        }
    }
    #pragma unroll
    for (int i = 0; i < 4; i++) {
        size_t m = (size_t)(b*KK + ty*4 + i);
        #pragma unroll
        for (int c = 0; c < 8; c++) {
            int cc = col0 + tx*8 + c;
            float v = acc[i][c] + Ytop[m*ncols + cc] + bias[cc];
            out[m*ncols + cc] = fmaxf(v, 0.f);
        }
    }
}

// classifier tail: PReLU + Linear(256,2) + softmax(2) -> pred
__global__ void k_head(const float* __restrict__ bc1,
                       const float* __restrict__ prelu_a,
                       const float* __restrict__ Wc2,
                       const float* __restrict__ bc2,
                       float* __restrict__ pred_out)
{
    __shared__ float s0[256], s1[256];
    int m = blockIdx.x;
    int c = threadIdx.x;
    float h = g_Hc[(size_t)m*HH2 + c] + bc1[c];
    h = (h >= 0.f) ? h : prelu_a[c]*h;
    s0[c] = h * Wc2[2*c];
    s1[c] = h * Wc2[2*c + 1];
    __syncthreads();
    for (int o = 128; o > 0; o >>= 1) {
        if (c < o) { s0[c] += s0[c + o]; s1[c] += s1[c + o]; }
        __syncthreads();
    }
    if (c == 0) {
        float l0 = s0[0] + bc2[0];
        float l1 = s1[0] + bc2[1];
        float mx = fmaxf(l0, l1);
        float e0 = expf(l0 - mx), e1 = expf(l1 - mx);
        float inv = 1.0f / (e0 + e1);
        pred_out[2*m]     = e0*inv;
        pred_out[2*m + 1] = e1*inv;
    }
}

// ---------------- launch -----------------------------------------------------

extern "C" void kernel_launch(void* const* d_in, const int* in_sizes, int n_in,
                              void* d_out, int out_size)
{
    const int*   indexes  = (const int*)  d_in[0];
    const float* features = (const float*)d_in[1];
    const int*   labels   = (const int*)  d_in[2];
    // d_in[3]=domain, d_in[4]=ori_0 : unused
    const int*   knn      = (const int*)  d_in[5];
    const float* all_pred = (const float*)d_in[6];
    const float* W1  = (const float*)d_in[7];
    const float* b1  = (const float*)d_in[8];
    const float* W2  = (const float*)d_in[9];
    const float* b2  = (const float*)d_in[10];
    const float* Wc1 = (const float*)d_in[11];
    const float* bc1 = (const float*)d_in[12];
    const float* pa  = (const float*)d_in[13];
    const float* Wc2 = (const float*)d_in[14];
    const float* bc2 = (const float*)d_in[15];

    float* out = (float*)d_out;
    float* pred_out = out;                 // [B*K*2]
    float* simm_out = out + (size_t)MM*2;  // [C]

    float *pX, *pX1, *pX2, *pYtop, *pYbot, *pZtop, *pZbot, *pHc;
    cudaGetSymbolAddress((void**)&pX,    g_X);
    cudaGetSymbolAddress((void**)&pX1,   g_X1);
    cudaGetSymbolAddress((void**)&pX2,   g_X2);
    cudaGetSymbolAddress((void**)&pYtop, g_Ytop);
    cudaGetSymbolAddress((void**)&pYbot, g_Ybot);
    cudaGetSymbolAddress((void**)&pZtop, g_Ztop);
    cudaGetSymbolAddress((void**)&pZbot, g_Zbot);
    cudaGetSymbolAddress((void**)&pHc,   g_Hc);

    // 1. cluster means + simm
    k_zero<<<8192, 256>>>();
    k_segsum<<<NPTS, 256>>>(features, labels);
    k_count<<<(NPTS + 255)/256, 256>>>(labels);
    k_finalize<<<CC, 256>>>(simm_out);

    // 2. per-batch gram, adjacency, normalized node features
    k_gram<<<BB, 256>>>(features, labels, knn, indexes);
    k_buildA<<<BB*KK, KK>>>(all_pred);
    k_buildX<<<BB*KK, 256>>>(features, labels, knn, indexes);

    // 3. layer 1: Ytop = X@W1[:2048], Ybot = X@W1[2048:], X1 = relu(Ytop + A@Ybot + b1)
    k_sgemm<<<dim3(NHID/128, MM/128), 256>>>(MM, DD, NHID, pX, DD, W1, NHID, pYtop, NHID);
    k_sgemm<<<dim3(NHID/128, MM/128), 256>>>(MM, DD, NHID, pX, DD, W1 + (size_t)DD*NHID, NHID, pYbot, NHID);
    k_combine<<<dim3(NHID/128, BB), 256>>>(pYtop, pYbot, b1, pX1, NHID);

    // 4. layer 2
    k_sgemm<<<dim3(HH2/128, MM/128), 256>>>(MM, NHID, HH2, pX1, NHID, W2, HH2, pZtop, HH2);
    k_sgemm<<<dim3(HH2/128, MM/128), 256>>>(MM, NHID, HH2, pX1, NHID, W2 + (size_t)NHID*HH2, HH2, pZbot, HH2);
    k_combine<<<dim3(HH2/128, BB), 256>>>(pZtop, pZbot, b2, pX2, HH2);

    // 5. classifier
    k_sgemm<<<dim3(HH2/128, MM/128), 256>>>(MM, HH2, HH2, pX2, HH2, Wc1, HH2, pHc, HH2);
    k_head<<<MM, 256>>>(bc1, pa, Wc2, bc2, pred_out);

    (void)in_sizes; (void)n_in; (void)out_size;
}

// round 3
// speedup vs baseline: 1.7643x; 1.7643x over previous
#include <cuda_runtime.h>
#include <math.h>

#define BB   256
#define KK   64
#define DD   2048
#define NPTS 50000
#define CC   5000
#define NHID 512
#define HH2  256
#define MM   (BB*KK)        // 16384
#define MU   5376           // padded unique rows: 5000 clusters + 256 pivots + pad

// ---------------- scratch (device globals; no allocations allowed) ----------
__device__ float g_clu[(size_t)CC*DD];        // cluster sum -> mean (raw, for gram)
__device__ float g_cnt[CC];
__device__ float g_Cn[(size_t)MU*DD];         // normalized unique rows (pad rows stay 0)
__device__ float g_G[(size_t)BB*KK*KK];       // raw gram per batch
__device__ float g_Adj[(size_t)BB*KK*KK];     // softmax adjacency
__device__ int   g_row[MM];                   // (b,k) -> unique-row index
__device__ float g_U[(size_t)2*MU*NHID];      // [Utop ; Ubot]
__device__ float g_X1[(size_t)MM*NHID];
__device__ float g_Z[(size_t)2*MM*HH2];       // [Ztop ; Zbot]
__device__ float g_X2[(size_t)MM*HH2];
__device__ float g_Hc[(size_t)MM*HH2];

// ---------------- kernels ---------------------------------------------------

__global__ void k_zero()
{
    size_t total = (size_t)CC*DD + CC;
    for (size_t i = (size_t)blockIdx.x*blockDim.x + threadIdx.x; i < total;
         i += (size_t)gridDim.x*blockDim.x) {
        if (i < (size_t)CC*DD) g_clu[i] = 0.f;
        else                   g_cnt[i - (size_t)CC*DD] = 0.f;
    }
}

// one block per feature row; coalesced atomic adds into the label's row
__global__ void k_segsum(const float* __restrict__ feats,
                         const int* __restrict__ labels)
{
    int row = blockIdx.x;
    int lab = labels[row];
    const float* src = feats + (size_t)row*DD;
    float* dst = g_clu + (size_t)lab*DD;
    #pragma unroll
    for (int j = 0; j < DD/256; j++) {
        int d = threadIdx.x + j*256;
        atomicAdd(&dst[d], src[d]);
    }
}

__global__ void k_count(const int* __restrict__ labels)
{
    int i = blockIdx.x*blockDim.x + threadIdx.x;
    if (i < NPTS) atomicAdd(&g_cnt[labels[i]], 1.0f);
}

// mean into g_clu, simm out, normalized mean into g_Cn
__global__ void k_finalize(float* __restrict__ simm_out)
{
    __shared__ float red[256];
    int c = blockIdx.x;
    float invn = 1.0f / fmaxf(g_cnt[c], 1.0f);
    float* rowm = g_clu + (size_t)c*DD;
    float vals[DD/256];
    float ss = 0.f;
    #pragma unroll
    for (int j = 0; j < DD/256; j++) {
        int d = threadIdx.x + j*256;
        float v = rowm[d] * invn;
        rowm[d] = v;
        vals[j] = v;
        ss += v*v;
    }
    red[threadIdx.x] = ss;
    __syncthreads();
    for (int o = 128; o > 0; o >>= 1) {
        if (threadIdx.x < o) red[threadIdx.x] += red[threadIdx.x + o];
        __syncthreads();
    }
    float s = red[0];
    if (threadIdx.x == 0) simm_out[c] = s;
    float inv = (s > 0.f) ? rsqrtf(s) : 0.f;
    float* cn = g_Cn + (size_t)c*DD;
    #pragma unroll
    for (int j = 0; j < DD/256; j++) {
        int d = threadIdx.x + j*256;
        cn[d] = vals[j] * inv;
    }
}

// normalized pivot features into g_Cn rows [CC, CC+BB)
__global__ void k_pivot(const float* __restrict__ feats,
                        const int* __restrict__ indexes)
{
    __shared__ float red[256];
    int b = blockIdx.x;
    const float* f = feats + (size_t)indexes[b]*DD;
    float vals[DD/256];
    float ss = 0.f;
    #pragma unroll
    for (int j = 0; j < DD/256; j++) {
        int d = threadIdx.x + j*256;
        float v = f[d];
        vals[j] = v;
        ss += v*v;
    }
    red[threadIdx.x] = ss;
    __syncthreads();
    for (int o = 128; o > 0; o >>= 1) {
        if (threadIdx.x < o) red[threadIdx.x] += red[threadIdx.x + o];
        __syncthreads();
    }
    float inv = rsqrtf(red[0]);
    float* cn = g_Cn + (size_t)(CC + b)*DD;
    #pragma unroll
    for (int j = 0; j < DD/256; j++) {
        int d = threadIdx.x + j*256;
        cn[d] = vals[j] * inv;
    }
}

__global__ void k_rowmap(const int* __restrict__ labels,
                         const int* __restrict__ knn)
{
    int i = blockIdx.x*blockDim.x + threadIdx.x;
    if (i >= MM) return;
    int b = i / KK, k = i % KK;
    g_row[i] = (k == 0) ? (CC + b) : labels[knn[i]];
}

// per-batch raw gram G = F F^T  (F rows gathered: row0=features[idx], else clu_mean)
__global__ __launch_bounds__(256)
void k_gram(const float* __restrict__ feats,
            const int* __restrict__ labels,
            const int* __restrict__ knn,
            const int* __restrict__ indexes)
{
    __shared__ const float* rowp[KK];
    __shared__ float Fs[KK][129];
    int b = blockIdx.x;
    int t = threadIdx.x;
    if (t < KK) {
        if (t == 0) rowp[0] = feats + (size_t)indexes[b]*DD;
        else        rowp[t] = g_clu + (size_t)labels[knn[b*KK + t]]*DD;
    }
    __syncthreads();

    float acc[4][4];
    #pragma unroll
    for (int i = 0; i < 4; i++)
        #pragma unroll
        for (int j = 0; j < 4; j++) acc[i][j] = 0.f;

    int tx = t & 15, ty = t >> 4;

    for (int d0 = 0; d0 < DD; d0 += 128) {
        for (int idx = t; idx < KK*128; idx += 256) {
            int r = idx >> 7, c = idx & 127;
            Fs[r][c] = rowp[r][d0 + c];
        }
        __syncthreads();
        #pragma unroll 4
        for (int d = 0; d < 128; d++) {
            float a[4], bv[4];
            #pragma unroll
            for (int i = 0; i < 4; i++) a[i]  = Fs[ty*4 + i][d];
            #pragma unroll
            for (int i = 0; i < 4; i++) bv[i] = Fs[tx*4 + i][d];
            #pragma unroll
            for (int i = 0; i < 4; i++)
                #pragma unroll
                for (int j = 0; j < 4; j++)
                    acc[i][j] = fmaf(a[i], bv[j], acc[i][j]);
        }
        __syncthreads();
    }
    float* Gb = g_G + (size_t)b*KK*KK;
    #pragma unroll
    for (int i = 0; i < 4; i++)
        #pragma unroll
        for (int j = 0; j < 4; j++)
            Gb[(ty*4 + i)*KK + (tx*4 + j)] = acc[i][j];
}

// adjacency: A = softmax_j( G[k][j] * exp(all_pred[b][j][1]) )
__global__ void k_buildA(const float* __restrict__ all_pred)
{
    __shared__ float red[KK];
    int b = blockIdx.x / KK;
    int k = blockIdx.x % KK;
    int j = threadIdx.x;
    float v = g_G[(size_t)b*KK*KK + k*KK + j] * expf(all_pred[(b*KK + j)*2 + 1]);
    red[j] = v;
    __syncthreads();
    for (int o = 32; o > 0; o >>= 1) {
        if (j < o) red[j] = fmaxf(red[j], red[j + o]);
        __syncthreads();
    }
    float mx = red[0];
    __syncthreads();
    float e = expf(v - mx);
    red[j] = e;
    __syncthreads();
    for (int o = 32; o > 0; o >>= 1) {
        if (j < o) red[j] += red[j + o];
        __syncthreads();
    }
    g_Adj[(size_t)b*KK*KK + k*KK + j] = e / red[0];
}

// 128x128x8 SGEMM, 8x8 microtile, row-major, z-fused over two (B,C) pairs.
__global__ __launch_bounds__(256)
void k_sgemmz(int Kd,
              const float* __restrict__ A, int lda,
              const float* __restrict__ B, int ldb, size_t Bz,
              float* __restrict__ C, int ldc, size_t Cz)
{
    B += (size_t)blockIdx.z * Bz;
    C += (size_t)blockIdx.z * Cz;

    __shared__ float As[8][132];
    __shared__ float Bs[8][128];
    const int t  = threadIdx.x;
    const int tx = t & 15, ty = t >> 4;
    const int row0 = blockIdx.y * 128;
    const int col0 = blockIdx.x * 128;

    const int arow = t >> 1;
    const int akk  = (t & 1) << 2;
    const int bkk  = t >> 5;
    const int bcol = (t & 31) << 2;

    const float* Ap = A + (size_t)(row0 + arow)*lda + akk;
    const float* Bp = B + (size_t)bkk*ldb + col0 + bcol;

    float acc[8][8];
    #pragma unroll
    for (int i = 0; i < 8; i++)
        #pragma unroll
        for (int j = 0; j < 8; j++) acc[i][j] = 0.f;

    for (int k0 = 0; k0 < Kd; k0 += 8) {
        float4 av = *(const float4*)Ap;  Ap += 8;
        float4 bv = *(const float4*)Bp;  Bp += (size_t)8*ldb;
        As[akk+0][arow] = av.x;
        As[akk+1][arow] = av.y;
        As[akk+2][arow] = av.z;
        As[akk+3][arow] = av.w;
        *(float4*)&Bs[bkk][bcol] = bv;
        __syncthreads();
        #pragma unroll
        for (int kk = 0; kk < 8; kk++) {
            float4 a0 = *(const float4*)&As[kk][ty*8];
            float4 a1 = *(const float4*)&As[kk][ty*8 + 4];
            float4 b0 = *(const float4*)&Bs[kk][tx*8];
            float4 b1 = *(const float4*)&Bs[kk][tx*8 + 4];
            float af[8] = {a0.x,a0.y,a0.z,a0.w,a1.x,a1.y,a1.z,a1.w};
            float bf[8] = {b0.x,b0.y,b0.z,b0.w,b1.x,b1.y,b1.z,b1.w};
            #pragma unroll
            for (int i = 0; i < 8; i++)
                #pragma unroll
                for (int j = 0; j < 8; j++)
                    acc[i][j] = fmaf(af[i], bf[j], acc[i][j]);
        }
        __syncthreads();
    }
    #pragma unroll
    for (int i = 0; i < 8; i++) {
        size_t r = (size_t)(row0 + ty*8 + i);
        #pragma unroll
        for (int j = 0; j < 8; j += 4) {
            float4 v = {acc[i][j], acc[i][j+1], acc[i][j+2], acc[i][j+3]};
            *(float4*)&C[r*ldc + col0 + tx*8 + j] = v;
        }
    }
}

// layer-1 combine with gather + pivot subtraction (ncols = NHID = 512):
// X1[b,k,c] = relu( Utop[r(b,k),c] - Utop[piv,c]
//                 + sum_j A[b,k,j]*Ubot[r(b,j),c] - Ubot[piv,c] + b1[c] )
__global__ __launch_bounds__(256)
void k_combine1(const float* __restrict__ Utop,
                const float* __restrict__ Ubot,
                const float* __restrict__ bias,
                float* __restrict__ out)
{
    __shared__ float As[KK][KK];
    __shared__ float Bs[32][128];
    __shared__ int   rows[KK];
    int b    = blockIdx.y;
    int col0 = blockIdx.x * 128;
    int t = threadIdx.x;
    int tx = t & 15, ty = t >> 4;

    const float* Ab = g_Adj + (size_t)b*KK*KK;
    for (int idx = t; idx < KK*KK; idx += 256)
        As[idx >> 6][idx & 63] = Ab[idx];
    if (t < KK) rows[t] = g_row[b*KK + t];
    __syncthreads();

    int piv = CC + b;
    int cc  = col0 + tx*8;
    float4 upa = *(const float4*)&Utop[(size_t)piv*NHID + cc];
    float4 upb = *(const float4*)&Utop[(size_t)piv*NHID + cc + 4];
    float4 uba = *(const float4*)&Ubot[(size_t)piv*NHID + cc];
    float4 ubb = *(const float4*)&Ubot[(size_t)piv*NHID + cc + 4];
    float up[8] = {upa.x,upa.y,upa.z,upa.w,upb.x,upb.y,upb.z,upb.w};
    float ub[8] = {uba.x,uba.y,uba.z,uba.w,ubb.x,ubb.y,ubb.z,ubb.w};

    float acc[4][8];
    #pragma unroll
    for (int i = 0; i < 4; i++)
        #pragma unroll
        for (int c = 0; c < 8; c++) acc[i][c] = 0.f;

    for (int jt = 0; jt < KK; jt += 32) {
        #pragma unroll
        for (int i = 0; i < 4; i++) {
            int idx = t + i*256;
            int j = idx >> 5, c4 = idx & 31;
            *(float4*)&Bs[j][c4*4] =
                *(const float4*)&Ubot[(size_t)rows[jt + j]*NHID + col0 + c4*4];
        }
        __syncthreads();
        #pragma unroll 4
        for (int j = 0; j < 32; j++) {
            float a[4];
            #pragma unroll
            for (int i = 0; i < 4; i++) a[i] = As[ty*4 + i][jt + j];
            float4 b0 = *(const float4*)&Bs[j][tx*8];
            float4 b1 = *(const float4*)&Bs[j][tx*8 + 4];
            float bf[8] = {b0.x,b0.y,b0.z,b0.w,b1.x,b1.y,b1.z,b1.w};
            #pragma unroll
            for (int i = 0; i < 4; i++)
                #pragma unroll
                for (int c = 0; c < 8; c++)
                    acc[i][c] = fmaf(a[i], bf[c], acc[i][c]);
        }
        __syncthreads();
    }
    #pragma unroll
    for (int i = 0; i < 4; i++) {
        int k = ty*4 + i;
        size_t m = (size_t)(b*KK + k);
        const float* ut = &Utop[(size_t)rows[k]*NHID + cc];
        float4 t0 = *(const float4*)ut;
        float4 t1 = *(const float4*)(ut + 4);
        float uv[8] = {t0.x,t0.y,t0.z,t0.w,t1.x,t1.y,t1.z,t1.w};
        #pragma unroll
        for (int c = 0; c < 8; c++) {
            float v = acc[i][c] + uv[c] - up[c] - ub[c] + bias[cc + c];
            out[m*NHID + cc + c] = fmaxf(v, 0.f);
        }
    }
}

// layer-2 combine (direct rows): out = relu(Ytop + A@Ybot + bias)
__global__ __launch_bounds__(256)
void k_combine(const float* __restrict__ Ytop,
               const float* __restrict__ Ybot,
               const float* __restrict__ bias,
               float* __restrict__ out, int ncols)
{
    __shared__ float As[KK][KK];
    __shared__ float Bs[32][128];
    int b    = blockIdx.y;
    int col0 = blockIdx.x * 128;
    int t = threadIdx.x;
    int tx = t & 15, ty = t >> 4;

    const float* Ab = g_Adj + (size_t)b*KK*KK;
    for (int idx = t; idx < KK*KK; idx += 256)
        As[idx >> 6][idx & 63] = Ab[idx];

    float acc[4][8];
    #pragma unroll
    for (int i = 0; i < 4; i++)
        #pragma unroll
        for (int c = 0; c < 8; c++) acc[i][c] = 0.f;

    for (int jt = 0; jt < KK; jt += 32) {
        __syncthreads();
        #pragma unroll
        for (int i = 0; i < 4; i++) {
            int idx = t + i*256;
            int j = idx >> 5, c4 = idx & 31;
            *(float4*)&Bs[j][c4*4] =
                *(const float4*)&Ybot[((size_t)(b*KK + jt + j))*ncols + col0 + c4*4];
        }
        __syncthreads();
        #pragma unroll 4
        for (int j = 0; j < 32; j++) {
            float a[4];
            #pragma unroll
            for (int i = 0; i < 4; i++) a[i] = As[ty*4 + i][jt + j];
            float4 b0 = *(const float4*)&Bs[j][tx*8];
            float4 b1 = *(const float4*)&Bs[j][tx*8 + 4];
            float bf[8] = {b0.x,b0.y,b0.z,b0.w,b1.x,b1.y,b1.z,b1.w};
            #pragma unroll
            for (int i = 0; i < 4; i++)
                #pragma unroll
                for (int c = 0; c < 8; c++)
                    acc[i][c] = fmaf(a[i], bf[c], acc[i][c]);
        }
    }
    #pragma unroll
    for (int i = 0; i < 4; i++) {
        size_t m = (size_t)(b*KK + ty*4 + i);
        #pragma unroll
        for (int c = 0; c < 8; c++) {
            int cc = col0 + tx*8 + c;
            float v = acc[i][c] + Ytop[m*ncols + cc] + bias[cc];
            out[m*ncols + cc] = fmaxf(v, 0.f);
        }
    }
}

// classifier tail: PReLU + Linear(256,2) + softmax(2) -> pred
__global__ void k_head(const float* __restrict__ bc1,
                       const float* __restrict__ prelu_a,
                       const float* __restrict__ Wc2,
                       const float* __restrict__ bc2,
                       float* __restrict__ pred_out)
{
    __shared__ float s0[256], s1[256];
    int m = blockIdx.x;
    int c = threadIdx.x;
    float h = g_Hc[(size_t)m*HH2 + c] + bc1[c];
    h = (h >= 0.f) ? h : prelu_a[c]*h;
    s0[c] = h * Wc2[2*c];
    s1[c] = h * Wc2[2*c + 1];
    __syncthreads();
    for (int o = 128; o > 0; o >>= 1) {
        if (c < o) { s0[c] += s0[c + o]; s1[c] += s1[c + o]; }
        __syncthreads();
    }
    if (c == 0) {
        float l0 = s0[0] + bc2[0];
        float l1 = s1[0] + bc2[1];
        float mx = fmaxf(l0, l1);
        float e0 = expf(l0 - mx), e1 = expf(l1 - mx);
        float inv = 1.0f / (e0 + e1);
        pred_out[2*m]     = e0*inv;
        pred_out[2*m + 1] = e1*inv;
    }
}

// ---------------- launch -----------------------------------------------------

extern "C" void kernel_launch(void* const* d_in, const int* in_sizes, int n_in,
                              void* d_out, int out_size)
{
    const int*   indexes  = (const int*)  d_in[0];
    const float* features = (const float*)d_in[1];
    const int*   labels   = (const int*)  d_in[2];
    // d_in[3]=domain, d_in[4]=ori_0 : unused
    const int*   knn      = (const int*)  d_in[5];
    const float* all_pred = (const float*)d_in[6];
    const float* W1  = (const float*)d_in[7];
    const float* b1  = (const float*)d_in[8];
    const float* W2  = (const float*)d_in[9];
    const float* b2  = (const float*)d_in[10];
    const float* Wc1 = (const float*)d_in[11];
    const float* bc1 = (const float*)d_in[12];
    const float* pa  = (const float*)d_in[13];
    const float* Wc2 = (const float*)d_in[14];
    const float* bc2 = (const float*)d_in[15];

    float* out = (float*)d_out;
    float* pred_out = out;                 // [B*K*2]
    float* simm_out = out + (size_t)MM*2;  // [C]

    float *pCn, *pU, *pX1, *pZ, *pX2, *pHc;
    cudaGetSymbolAddress((void**)&pCn, g_Cn);
    cudaGetSymbolAddress((void**)&pU,  g_U);
    cudaGetSymbolAddress((void**)&pX1, g_X1);
    cudaGetSymbolAddress((void**)&pZ,  g_Z);
    cudaGetSymbolAddress((void**)&pX2, g_X2);
    cudaGetSymbolAddress((void**)&pHc, g_Hc);

    float* pUtop = pU;
    float* pUbot = pU + (size_t)MU*NHID;
    float* pZtop = pZ;
    float* pZbot = pZ + (size_t)MM*HH2;

    // 1. cluster means, simm, normalized unique rows
    k_zero<<<8192, 256>>>();
    k_segsum<<<NPTS, 256>>>(features, labels);
    k_count<<<(NPTS + 255)/256, 256>>>(labels);
    k_finalize<<<CC, 256>>>(simm_out);
    k_pivot<<<BB, 256>>>(features, indexes);
    k_rowmap<<<(MM + 255)/256, 256>>>(labels, knn);

    // 2. per-batch gram + adjacency
    k_gram<<<BB, 256>>>(features, labels, knn, indexes);
    k_buildA<<<BB*KK, KK>>>(all_pred);

    // 3. layer 1 on UNIQUE rows: U{top,bot} = Cn @ W1{top,bot}, then gathered combine
    k_sgemmz<<<dim3(NHID/128, MU/128, 2), 256>>>(
        DD, pCn, DD, W1, NHID, (size_t)DD*NHID, pU, NHID, (size_t)MU*NHID);
    k_combine1<<<dim3(NHID/128, BB), 256>>>(pUtop, pUbot, b1, pX1);

    // 4. layer 2 (dense rows)
    k_sgemmz<<<dim3(HH2/128, MM/128, 2), 256>>>(
        NHID, pX1, NHID, W2, HH2, (size_t)NHID*HH2, pZ, HH2, (size_t)MM*HH2);
    k_combine<<<dim3(HH2/128, BB), 256>>>(pZtop, pZbot, b2, pX2, HH2);

    // 5. classifier
    k_sgemmz<<<dim3(HH2/128, MM/128, 1), 256>>>(
        HH2, pX2, HH2, Wc1, HH2, 0, pHc, HH2, 0);
    k_head<<<MM, 256>>>(bc1, pa, Wc2, bc2, pred_out);

    (void)in_sizes; (void)n_in; (void)out_size;
}

// round 5
// speedup vs baseline: 2.8639x; 1.6232x over previous
#include <cuda_runtime.h>
#include <cuda_bf16.h>
#include <math.h>
#include <stdint.h>

#define BB   256
#define KK   64
#define DD   2048
#define NPTS 50000
#define CC   5000
#define NHID 512
#define HH2  256
#define MM   (BB*KK)        // 16384
#define MU   5376           // padded unique rows: 5000 clusters + 256 pivots + pad

// ---------------- scratch (device globals; no allocations allowed) ----------
__device__ float g_clu[(size_t)CC*DD];        // cluster mean (raw, for gram)
__device__ float g_cnt[CC];
__device__ __nv_bfloat16 g_A1h[(size_t)MU*DD];   // normalized unique rows hi/lo
__device__ __nv_bfloat16 g_A1l[(size_t)MU*DD];
__device__ __nv_bfloat16 g_W1h[(size_t)1024*DD]; // W1^T fused [1024 x 2048]
__device__ __nv_bfloat16 g_W1l[(size_t)1024*DD];
__device__ __nv_bfloat16 g_W2h[(size_t)512*NHID];
__device__ __nv_bfloat16 g_W2l[(size_t)512*NHID];
__device__ __nv_bfloat16 g_Wch[(size_t)HH2*HH2];
__device__ __nv_bfloat16 g_Wcl[(size_t)HH2*HH2];
__device__ float g_U [(size_t)MU*1024];       // layer1 unique-row outputs [top|bot]
__device__ __nv_bfloat16 g_X1h[(size_t)MM*NHID];
__device__ __nv_bfloat16 g_X1l[(size_t)MM*NHID];
__device__ float g_Z [(size_t)MM*NHID];       // layer2 outputs [top|bot] per row
__device__ __nv_bfloat16 g_X2h[(size_t)MM*HH2];
__device__ __nv_bfloat16 g_X2l[(size_t)MM*HH2];
__device__ float g_Hc[(size_t)MM*HH2];
__device__ float g_G  [(size_t)BB*KK*KK];
__device__ float g_Adj[(size_t)BB*KK*KK];
__device__ int   g_row[MM];

// ---------------- helpers -----------------------------------------------------

__device__ __forceinline__ uint32_t smem_u32(const void* p) {
    uint32_t a;
    asm("{ .reg .u64 t; cvta.to.shared.u64 t, %1; cvt.u32.u64 %0, t; }"
        : "=r"(a) : "l"(p));
    return a;
}

#define CP_ASYNC16(saddr, gaddr) \
    asm volatile("cp.async.cg.shared.global [%0], [%1], 16;\n" \
                 :: "r"(saddr), "l"(gaddr))
#define CP_COMMIT() asm volatile("cp.async.commit_group;\n" ::: "memory")
#define CP_WAIT0()  asm volatile("cp.async.wait_group 0;\n" ::: "memory")
#define CP_WAIT1()  asm volatile("cp.async.wait_group 1;\n" ::: "memory")

#define LDMATRIX_X4(d0,d1,d2,d3, addr) \
    asm volatile("ldmatrix.sync.aligned.m8n8.x4.shared.b16 {%0,%1,%2,%3}, [%4];\n" \
        : "=r"(d0), "=r"(d1), "=r"(d2), "=r"(d3) : "r"(addr))

#define MMA16816(c, a, b0v, b1v) \
    asm volatile("mma.sync.aligned.m16n8k16.row.col.f32.bf16.bf16.f32 " \
        "{%0,%1,%2,%3}, {%4,%5,%6,%7}, {%8,%9}, {%0,%1,%2,%3};\n" \
        : "+f"((c)[0]), "+f"((c)[1]), "+f"((c)[2]), "+f"((c)[3]) \
        : "r"((a)[0]), "r"((a)[1]), "r"((a)[2]), "r"((a)[3]), \
          "r"(b0v), "r"(b1v))

// ---------------- prep kernels ----------------------------------------------

__global__ void k_zero()
{
    size_t total = (size_t)CC*DD + CC;
    for (size_t i = (size_t)blockIdx.x*blockDim.x + threadIdx.x; i < total;
         i += (size_t)gridDim.x*blockDim.x) {
        if (i < (size_t)CC*DD) g_clu[i] = 0.f;
        else                   g_cnt[i - (size_t)CC*DD] = 0.f;
    }
}

__global__ void k_segsum(const float* __restrict__ feats,
                         const int* __restrict__ labels)
{
    int row = blockIdx.x;
    int lab = labels[row];
    const float* src = feats + (size_t)row*DD;
    float* dst = g_clu + (size_t)lab*DD;
    #pragma unroll
    for (int j = 0; j < DD/256; j++) {
        int d = threadIdx.x + j*256;
        atomicAdd(&dst[d], src[d]);
    }
}

__global__ void k_count(const int* __restrict__ labels)
{
    int i = blockIdx.x*blockDim.x + threadIdx.x;
    if (i < NPTS) atomicAdd(&g_cnt[labels[i]], 1.0f);
}

// mean into g_clu, simm out, normalized mean -> bf16 hi/lo into A1 rows [0,CC)
__global__ void k_finalize(float* __restrict__ simm_out)
{
    __shared__ float red[256];
    int c = blockIdx.x;
    float invn = 1.0f / fmaxf(g_cnt[c], 1.0f);
    float* rowm = g_clu + (size_t)c*DD;
    float vals[DD/256];
    float ss = 0.f;
    #pragma unroll
    for (int j = 0; j < DD/256; j++) {
        int d = threadIdx.x + j*256;
        float v = rowm[d] * invn;
        rowm[d] = v;
        vals[j] = v;
        ss += v*v;
    }
    red[threadIdx.x] = ss;
    __syncthreads();
    for (int o = 128; o > 0; o >>= 1) {
        if (threadIdx.x < o) red[threadIdx.x] += red[threadIdx.x + o];
        __syncthreads();
    }
    float s = red[0];
    if (threadIdx.x == 0) simm_out[c] = s;
    float inv = (s > 0.f) ? rsqrtf(s) : 0.f;
    #pragma unroll
    for (int j = 0; j < DD/256; j++) {
        int d = threadIdx.x + j*256;
        float v = vals[j] * inv;
        __nv_bfloat16 h = __float2bfloat16(v);
        g_A1h[(size_t)c*DD + d] = h;
        g_A1l[(size_t)c*DD + d] = __float2bfloat16(v - __bfloat162float(h));
    }
}

// normalized pivot features -> A1 rows [CC, CC+BB)
__global__ void k_pivot(const float* __restrict__ feats,
                        const int* __restrict__ indexes)
{
    __shared__ float red[256];
    int b = blockIdx.x;
    const float* f = feats + (size_t)indexes[b]*DD;
    float vals[DD/256];
    float ss = 0.f;
    #pragma unroll
    for (int j = 0; j < DD/256; j++) {
        int d = threadIdx.x + j*256;
        float v = f[d];
        vals[j] = v;
        ss += v*v;
    }
    red[threadIdx.x] = ss;
    __syncthreads();
    for (int o = 128; o > 0; o >>= 1) {
        if (threadIdx.x < o) red[threadIdx.x] += red[threadIdx.x + o];
        __syncthreads();
    }
    float inv = rsqrtf(red[0]);
    size_t base = (size_t)(CC + b)*DD;
    #pragma unroll
    for (int j = 0; j < DD/256; j++) {
        int d = threadIdx.x + j*256;
        float v = vals[j] * inv;
        __nv_bfloat16 h = __float2bfloat16(v);
        g_A1h[base + d] = h;
        g_A1l[base + d] = __float2bfloat16(v - __bfloat162float(h));
    }
}

__global__ void k_rowmap(const int* __restrict__ labels,
                         const int* __restrict__ knn)
{
    int i = blockIdx.x*blockDim.x + threadIdx.x;
    if (i >= MM) return;
    int b = i / KK, k = i % KK;
    g_row[i] = (k == 0) ? (CC + b) : labels[knn[i]];
}

// weight transpose + bf16 split: dst[n][k] = src[(koff+k)*ldw + col]
__global__ void k_convW(const float* __restrict__ W, int ldw, int Kd, int Nh,
                        __nv_bfloat16* __restrict__ dh,
                        __nv_bfloat16* __restrict__ dl)
{
    size_t i = (size_t)blockIdx.x*blockDim.x + threadIdx.x;
    int n = (int)(i / Kd), k = (int)(i % Kd);
    int col  = (n < Nh) ? n : n - Nh;
    int koff = (n < Nh) ? 0 : Kd;
    float v = W[(size_t)(koff + k)*ldw + col];
    __nv_bfloat16 h = __float2bfloat16(v);
    dh[i] = h;
    dl[i] = __float2bfloat16(v - __bfloat162float(h));
}

// ---------------- gram + adjacency (fp32) ------------------------------------

__global__ __launch_bounds__(256)
void k_gram(const float* __restrict__ feats,
            const int* __restrict__ labels,
            const int* __restrict__ knn,
            const int* __restrict__ indexes)
{
    __shared__ const float* rowp[KK];
    __shared__ float Fs[KK][129];
    int b = blockIdx.x;
    int t = threadIdx.x;
    if (t < KK) {
        if (t == 0) rowp[0] = feats + (size_t)indexes[b]*DD;
        else        rowp[t] = g_clu + (size_t)labels[knn[b*KK + t]]*DD;
    }
    __syncthreads();

    float acc[4][4];
    #pragma unroll
    for (int i = 0; i < 4; i++)
        #pragma unroll
        for (int j = 0; j < 4; j++) acc[i][j] = 0.f;

    int tx = t & 15, ty = t >> 4;

    for (int d0 = 0; d0 < DD; d0 += 128) {
        for (int idx = t; idx < KK*128; idx += 256) {
            int r = idx >> 7, c = idx & 127;
            Fs[r][c] = rowp[r][d0 + c];
        }
        __syncthreads();
        #pragma unroll 4
        for (int d = 0; d < 128; d++) {
            float a[4], bv[4];
            #pragma unroll
            for (int i = 0; i < 4; i++) a[i]  = Fs[ty*4 + i][d];
            #pragma unroll
            for (int i = 0; i < 4; i++) bv[i] = Fs[tx*4 + i][d];
            #pragma unroll
            for (int i = 0; i < 4; i++)
                #pragma unroll
                for (int j = 0; j < 4; j++)
                    acc[i][j] = fmaf(a[i], bv[j], acc[i][j]);
        }
        __syncthreads();
    }
    float* Gb = g_G + (size_t)b*KK*KK;
    #pragma unroll
    for (int i = 0; i < 4; i++)
        #pragma unroll
        for (int j = 0; j < 4; j++)
            Gb[(ty*4 + i)*KK + (tx*4 + j)] = acc[i][j];
}

__global__ void k_buildA(const float* __restrict__ all_pred)
{
    __shared__ float red[KK];
    int b = blockIdx.x / KK;
    int k = blockIdx.x % KK;
    int j = threadIdx.x;
    float v = g_G[(size_t)b*KK*KK + k*KK + j] * expf(all_pred[(b*KK + j)*2 + 1]);
    red[j] = v;
    __syncthreads();
    for (int o = 32; o > 0; o >>= 1) {
        if (j < o) red[j] = fmaxf(red[j], red[j + o]);
        __syncthreads();
    }
    float mx = red[0];
    __syncthreads();
    float e = expf(v - mx);
    red[j] = e;
    __syncthreads();
    for (int o = 32; o > 0; o >>= 1) {
        if (j < o) red[j] += red[j + o];
        __syncthreads();
    }
    g_Adj[(size_t)b*KK*KK + k*KK + j] = e / red[0];
}

// ---------------- mma.sync bf16x3 GEMM ----------------------------------------
// C[M x Ncols] (fp32, row-major) = A (hi+lo) @ B^T (hi+lo); A:[M x Kd], B:[Ncols x Kd]
// 128x128 block tile, 8 warps (32x64 each), K-chunk 64, cp.async double buffer.

#define TSTRIDE 72                       // bf16 elems per smem row (144B, conflict-free)
#define TILE_E  (128*TSTRIDE)            // elems per tile
#define BUF_E   (4*TILE_E)               // elems per buffer (Ah,Al,Bh,Bl)
#define GEMM_SMEM (2*BUF_E*2)            // bytes, double buffered = 147456

__global__ __launch_bounds__(256)
void k_mma_gemm(int Kd,
                const __nv_bfloat16* __restrict__ Ah,
                const __nv_bfloat16* __restrict__ Al,
                const __nv_bfloat16* __restrict__ Bh,
                const __nv_bfloat16* __restrict__ Bl,
                float* __restrict__ C, int Ncols)
{
    extern __shared__ __nv_bfloat16 sm[];
    int t = threadIdx.x;
    int lane = t & 31, wid = t >> 5;
    int m0 = blockIdx.y*128, n0 = blockIdx.x*128;
    int wm = (wid & 3) * 32;
    int wn = (wid >> 2) * 64;

    uint32_t sbase = smem_u32(sm);

    // cp.async pattern: thread covers rows {r, r+32, r+64, r+96}, 16B column c16
    int lrow = t >> 3;
    int c16  = t & 7;
    const __nv_bfloat16* gsrc0 = Ah + (size_t)m0*Kd;
    const __nv_bfloat16* gsrc1 = Al + (size_t)m0*Kd;
    const __nv_bfloat16* gsrc2 = Bh + (size_t)n0*Kd;
    const __nv_bfloat16* gsrc3 = Bl + (size_t)n0*Kd;

    int nch = Kd >> 6;

    // ldmatrix lane->address components
    int g = lane >> 3, r = lane & 7;
    uint32_t a_row  = wm + ((g & 1) << 3) + r;
    uint32_t a_colB = (uint32_t)(((g >> 1) << 3) * 2);
    uint32_t b_row  = wn + ((g >> 1) << 3) + r;
    uint32_t b_colB = (uint32_t)(((g & 1) << 3) * 2);

    float acc[2][8][4];
    #pragma unroll
    for (int mi = 0; mi < 2; mi++)
        #pragma unroll
        for (int ni = 0; ni < 8; ni++)
            #pragma unroll
            for (int q = 0; q < 4; q++) acc[mi][ni][q] = 0.f;

    // prologue: issue chunks 0, 1
    #pragma unroll 1
    for (int pre = 0; pre < 2; pre++) {
        if (pre >= nch) break;
        uint32_t sb = sbase + (uint32_t)pre*(BUF_E*2);
        int k0 = pre << 6;
        #pragma unroll
        for (int i = 0; i < 4; i++) {
            int rr = lrow + i*32;
            size_t go = (size_t)rr*Kd + k0 + c16*8;
            uint32_t so = (uint32_t)(rr*TSTRIDE)*2 + (uint32_t)c16*16;
            CP_ASYNC16(sb + 0*TILE_E*2 + so, gsrc0 + go);
            CP_ASYNC16(sb + 1*TILE_E*2 + so, gsrc1 + go);
            CP_ASYNC16(sb + 2*TILE_E*2 + so, gsrc2 + go);
            CP_ASYNC16(sb + 3*TILE_E*2 + so, gsrc3 + go);
        }
        CP_COMMIT();
    }

    for (int ch = 0; ch < nch; ch++) {
        if (ch == nch - 1) CP_WAIT0(); else CP_WAIT1();
        __syncthreads();

        uint32_t sb  = sbase + (uint32_t)(ch & 1)*(BUF_E*2);
        uint32_t sAh = sb;
        uint32_t sAl = sb + 1*TILE_E*2;
        uint32_t sBh = sb + 2*TILE_E*2;
        uint32_t sBl = sb + 3*TILE_E*2;

        #pragma unroll
        for (int ks = 0; ks < 4; ks++) {
            uint32_t kb = (uint32_t)(ks*16*2);
            uint32_t ah[2][4], al[2][4];
            #pragma unroll
            for (int mi = 0; mi < 2; mi++) {
                uint32_t ra = (a_row + mi*16)*(TSTRIDE*2) + a_colB + kb;
                LDMATRIX_X4(ah[mi][0], ah[mi][1], ah[mi][2], ah[mi][3], sAh + ra);
                LDMATRIX_X4(al[mi][0], al[mi][1], al[mi][2], al[mi][3], sAl + ra);
            }
            uint32_t bh[4][4], bl[4][4];
            #pragma unroll
            for (int nj = 0; nj < 4; nj++) {
                uint32_t rb = (b_row + nj*16)*(TSTRIDE*2) + b_colB + kb;
                LDMATRIX_X4(bh[nj][0], bh[nj][1], bh[nj][2], bh[nj][3], sBh + rb);
                LDMATRIX_X4(bl[nj][0], bl[nj][1], bl[nj][2], bl[nj][3], sBl + rb);
            }
            #pragma unroll
            for (int mi = 0; mi < 2; mi++)
                #pragma unroll
                for (int ni = 0; ni < 8; ni++) {
                    int nj = ni >> 1, h = (ni & 1) * 2;
                    MMA16816(acc[mi][ni], ah[mi], bh[nj][h], bh[nj][h+1]);
                    MMA16816(acc[mi][ni], ah[mi], bl[nj][h], bl[nj][h+1]);
                    MMA16816(acc[mi][ni], al[mi], bh[nj][h], bh[nj][h+1]);
                }
        }
        __syncthreads();
        if (ch + 2 < nch) {
            uint32_t sb2 = sbase + (uint32_t)(ch & 1)*(BUF_E*2);
            int k0 = (ch + 2) << 6;
            #pragma unroll
            for (int i = 0; i < 4; i++) {
                int rr = lrow + i*32;
                size_t go = (size_t)rr*Kd + k0 + c16*8;
                uint32_t so = (uint32_t)(rr*TSTRIDE)*2 + (uint32_t)c16*16;
                CP_ASYNC16(sb2 + 0*TILE_E*2 + so, gsrc0 + go);
                CP_ASYNC16(sb2 + 1*TILE_E*2 + so, gsrc1 + go);
                CP_ASYNC16(sb2 + 2*TILE_E*2 + so, gsrc2 + go);
                CP_ASYNC16(sb2 + 3*TILE_E*2 + so, gsrc3 + go);
            }
            CP_COMMIT();
        }
    }

    // epilogue: fragment layout c0,c1 -> (row lane/4, col (lane%4)*2), c2,c3 -> row+8
    #pragma unroll
    for (int mi = 0; mi < 2; mi++) {
        int rr0 = m0 + wm + mi*16 + (lane >> 2);
        #pragma unroll
        for (int ni = 0; ni < 8; ni++) {
            int cc = n0 + wn + ni*8 + (lane & 3)*2;
            float2 v0 = { acc[mi][ni][0], acc[mi][ni][1] };
            float2 v1 = { acc[mi][ni][2], acc[mi][ni][3] };
            *(float2*)&C[(size_t)rr0*Ncols + cc]       = v0;
            *(float2*)&C[(size_t)(rr0 + 8)*Ncols + cc] = v1;
        }
    }
}

// ---------------- combines ----------------------------------------------------

__global__ __launch_bounds__(256)
void k_combine1(const float* __restrict__ bias)
{
    __shared__ float As[KK][KK];
    __shared__ float Bs[32][128];
    __shared__ int   rows[KK];
    int b    = blockIdx.y;
    int col0 = blockIdx.x * 128;
    int t = threadIdx.x;
    int tx = t & 15, ty = t >> 4;

    const float* Ab = g_Adj + (size_t)b*KK*KK;
    for (int idx = t; idx < KK*KK; idx += 256)
        As[idx >> 6][idx & 63] = Ab[idx];
    if (t < KK) rows[t] = g_row[b*KK + t];
    __syncthreads();

    int piv = CC + b;
    int cc  = col0 + tx*8;
    const float* Up = g_U + (size_t)piv*1024;
    float4 upa = *(const float4*)(Up + cc);
    float4 upb = *(const float4*)(Up + cc + 4);
    float4 uba = *(const float4*)(Up + 512 + cc);
    float4 ubb = *(const float4*)(Up + 512 + cc + 4);
    float up[8] = {upa.x,upa.y,upa.z,upa.w,upb.x,upb.y,upb.z,upb.w};
    float ub[8] = {uba.x,uba.y,uba.z,uba.w,ubb.x,ubb.y,ubb.z,ubb.w};

    float acc[4][8];
    #pragma unroll
    for (int i = 0; i < 4; i++)
        #pragma unroll
        for (int c = 0; c < 8; c++) acc[i][c] = 0.f;

    for (int jt = 0; jt < KK; jt += 32) {
        #pragma unroll
        for (int i = 0; i < 4; i++) {
            int idx = t + i*256;
            int j = idx >> 5, c4 = idx & 31;
            *(float4*)&Bs[j][c4*4] =
                *(const float4*)(g_U + (size_t)rows[jt + j]*1024 + 512 + col0 + c4*4);
        }
        __syncthreads();
        #pragma unroll 4
        for (int j = 0; j < 32; j++) {
            float a[4];
            #pragma unroll
            for (int i = 0; i < 4; i++) a[i] = As[ty*4 + i][jt + j];
            float4 b0 = *(const float4*)&Bs[j][tx*8];
            float4 b1 = *(const float4*)&Bs[j][tx*8 + 4];
            float bf[8] = {b0.x,b0.y,b0.z,b0.w,b1.x,b1.y,b1.z,b1.w};
            #pragma unroll
            for (int i = 0; i < 4; i++)
                #pragma unroll
                for (int c = 0; c < 8; c++)
                    acc[i][c] = fmaf(a[i], bf[c], acc[i][c]);
        }
        __syncthreads();
    }
    #pragma unroll
    for (int i = 0; i < 4; i++) {
        int k = ty*4 + i;
        size_t m = (size_t)(b*KK + k);
        const float* ut = g_U + (size_t)rows[k]*1024 + cc;
        float4 t0 = *(const float4*)ut;
        float4 t1 = *(const float4*)(ut + 4);
        float uv[8] = {t0.x,t0.y,t0.z,t0.w,t1.x,t1.y,t1.z,t1.w};
        #pragma unroll
        for (int c = 0; c < 8; c++) {
            float v = acc[i][c] + uv[c] - up[c] - ub[c] + bias[cc + c];
            v = fmaxf(v, 0.f);
            __nv_bfloat16 h = __float2bfloat16(v);
            g_X1h[m*NHID + cc + c] = h;
            g_X1l[m*NHID + cc + c] = __float2bfloat16(v - __bfloat162float(h));
        }
    }
}

__global__ __launch_bounds__(256)
void k_combine2(const float* __restrict__ bias)
{
    __shared__ float As[KK][KK];
    __shared__ float Bs[32][128];
    int b    = blockIdx.y;
    int col0 = blockIdx.x * 128;
    int t = threadIdx.x;
    int tx = t & 15, ty = t >> 4;

    const float* Ab = g_Adj + (size_t)b*KK*KK;
    for (int idx = t; idx < KK*KK; idx += 256)
        As[idx >> 6][idx & 63] = Ab[idx];

    float acc[4][8];
    #pragma unroll
    for (int i = 0; i < 4; i++)
        #pragma unroll
        for (int c = 0; c < 8; c++) acc[i][c] = 0.f;

    for (int jt = 0; jt < KK; jt += 32) {
        __syncthreads();
        #pragma unroll
        for (int i = 0; i < 4; i++) {
            int idx = t + i*256;
            int j = idx >> 5, c4 = idx & 31;
            *(float4*)&Bs[j][c4*4] =
                *(const float4*)(g_Z + (size_t)(b*KK + jt + j)*512 + 256 + col0 + c4*4);
        }
        __syncthreads();
        #pragma unroll 4
        for (int j = 0; j < 32; j++) {
            float a[4];
            #pragma unroll
            for (int i = 0; i < 4; i++) a[i] = As[ty*4 + i][jt + j];
            float4 b0 = *(const float4*)&Bs[j][tx*8];
            float4 b1 = *(const float4*)&Bs[j][tx*8 + 4];
            float bf[8] = {b0.x,b0.y,b0.z,b0.w,b1.x,b1.y,b1.z,b1.w};
            #pragma unroll
            for (int i = 0; i < 4; i++)
                #pragma unroll
                for (int c = 0; c < 8; c++)
                    acc[i][c] = fmaf(a[i], bf[c], acc[i][c]);
        }
    }
    #pragma unroll
    for (int i = 0; i < 4; i++) {
        size_t m = (size_t)(b*KK + ty*4 + i);
        #pragma unroll
        for (int c = 0; c < 8; c++) {
            int cc = col0 + tx*8 + c;
            float v = acc[i][c] + g_Z[m*512 + cc] + bias[cc];
            v = fmaxf(v, 0.f);
            __nv_bfloat16 h = __float2bfloat16(v);
            g_X2h[m*HH2 + cc] = h;
            g_X2l[m*HH2 + cc] = __float2bfloat16(v - __bfloat162float(h));
        }
    }
}

// classifier tail: PReLU + Linear(256,2) + softmax(2) -> pred
__global__ void k_head(const float* __restrict__ bc1,
                       const float* __restrict__ prelu_a,
                       const float* __restrict__ Wc2,
                       const float* __restrict__ bc2,
                       float* __restrict__ pred_out)
{
    __shared__ float s0[256], s1[256];
    int m = blockIdx.x;
    int c = threadIdx.x;
    float h = g_Hc[(size_t)m*HH2 + c] + bc1[c];
    h = (h >= 0.f) ? h : prelu_a[c]*h;
    s0[c] = h * Wc2[2*c];
    s1[c] = h * Wc2[2*c + 1];
    __syncthreads();
    for (int o = 128; o > 0; o >>= 1) {
        if (c < o) { s0[c] += s0[c + o]; s1[c] += s1[c + o]; }
        __syncthreads();
    }
    if (c == 0) {
        float l0 = s0[0] + bc2[0];
        float l1 = s1[0] + bc2[1];
        float mx = fmaxf(l0, l1);
        float e0 = expf(l0 - mx), e1 = expf(l1 - mx);
        float inv = 1.0f / (e0 + e1);
        pred_out[2*m]     = e0*inv;
        pred_out[2*m + 1] = e1*inv;
    }
}

// ---------------- launch -----------------------------------------------------

extern "C" void kernel_launch(void* const* d_in, const int* in_sizes, int n_in,
                              void* d_out, int out_size)
{
    const int*   indexes  = (const int*)  d_in[0];
    const float* features = (const float*)d_in[1];
    const int*   labels   = (const int*)  d_in[2];
    const int*   knn      = (const int*)  d_in[5];
    const float* all_pred = (const float*)d_in[6];
    const float* W1  = (const float*)d_in[7];
    const float* b1  = (const float*)d_in[8];
    const float* W2  = (const float*)d_in[9];
    const float* b2  = (const float*)d_in[10];
    const float* Wc1 = (const float*)d_in[11];
    const float* bc1 = (const float*)d_in[12];
    const float* pa  = (const float*)d_in[13];
    const float* Wc2 = (const float*)d_in[14];
    const float* bc2 = (const float*)d_in[15];

    float* out = (float*)d_out;
    float* pred_out = out;
    float* simm_out = out + (size_t)MM*2;

    cudaFuncSetAttribute(k_mma_gemm, cudaFuncAttributeMaxDynamicSharedMemorySize,
                         GEMM_SMEM);

    __nv_bfloat16 *pA1h,*pA1l,*pW1h,*pW1l,*pW2h,*pW2l,*pWch,*pWcl,*pX1h,*pX1l,*pX2h,*pX2l;
    float *pU,*pZ,*pHc;
    cudaGetSymbolAddress((void**)&pA1h, g_A1h);
    cudaGetSymbolAddress((void**)&pA1l, g_A1l);
    cudaGetSymbolAddress((void**)&pW1h, g_W1h);
    cudaGetSymbolAddress((void**)&pW1l, g_W1l);
    cudaGetSymbolAddress((void**)&pW2h, g_W2h);
    cudaGetSymbolAddress((void**)&pW2l, g_W2l);
    cudaGetSymbolAddress((void**)&pWch, g_Wch);
    cudaGetSymbolAddress((void**)&pWcl, g_Wcl);
    cudaGetSymbolAddress((void**)&pX1h, g_X1h);
    cudaGetSymbolAddress((void**)&pX1l, g_X1l);
    cudaGetSymbolAddress((void**)&pX2h, g_X2h);
    cudaGetSymbolAddress((void**)&pX2l, g_X2l);
    cudaGetSymbolAddress((void**)&pU,  g_U);
    cudaGetSymbolAddress((void**)&pZ,  g_Z);
    cudaGetSymbolAddress((void**)&pHc, g_Hc);

    // weight transposes + bf16 split (independent of data pipeline)
    k_convW<<<(1024u*DD)/256, 256>>>(W1, NHID, DD, NHID, pW1h, pW1l);
    k_convW<<<(512u*NHID)/256, 256>>>(W2, HH2, NHID, HH2, pW2h, pW2l);
    k_convW<<<(HH2*HH2)/256, 256>>>(Wc1, HH2, HH2, HH2, pWch, pWcl);

    // cluster means, simm, normalized unique rows (bf16 hi/lo)
    k_zero<<<8192, 256>>>();
    k_segsum<<<NPTS, 256>>>(features, labels);
    k_count<<<(NPTS + 255)/256, 256>>>(labels);
    k_finalize<<<CC, 256>>>(simm_out);
    k_pivot<<<BB, 256>>>(features, indexes);
    k_rowmap<<<(MM + 255)/256, 256>>>(labels, knn);

    // per-batch gram + adjacency
    k_gram<<<BB, 256>>>(features, labels, knn, indexes);
    k_buildA<<<BB*KK, KK>>>(all_pred);

    // layer 1: U = A1 @ W1t^T  (unique rows, fused top|bot N=1024)
    k_mma_gemm<<<dim3(1024/128, MU/128), 256, GEMM_SMEM>>>(
        DD, pA1h, pA1l, pW1h, pW1l, pU, 1024);
    k_combine1<<<dim3(NHID/128, BB), 256>>>(b1);

    // layer 2: Z = X1 @ W2t^T  (fused top|bot N=512)
    k_mma_gemm<<<dim3(512/128, MM/128), 256, GEMM_SMEM>>>(
        NHID, pX1h, pX1l, pW2h, pW2l, pZ, 512);
    k_combine2<<<dim3(HH2/128, BB), 256>>>(b2);

    // classifier: Hc = X2 @ Wc1t^T
    k_mma_gemm<<<dim3(HH2/128, MM/128), 256, GEMM_SMEM>>>(
        HH2, pX2h, pX2l, pWch, pWcl, pHc, 256);
    k_head<<<MM, 256>>>(bc1, pa, Wc2, bc2, pred_out);

    (void)in_sizes; (void)n_in; (void)out_size;
}

// round 6
// speedup vs baseline: 5.8544x; 2.0442x over previous
#include <cuda_runtime.h>
#include <cuda_bf16.h>
#include <math.h>
#include <stdint.h>

#define BB   256
#define KK   64
#define DD   2048
#define NPTS 50000
#define CC   5000
#define NHID 512
#define HH2  256
#define MM   (BB*KK)        // 16384
#define MU   5376           // padded unique rows: 5000 clusters + 256 pivots + pad

// ---------------- scratch (device globals; no allocations allowed) ----------
__device__ int   g_icnt[CC];
__device__ int   g_off[CC];
__device__ int   g_wptr[CC];
__device__ int   g_sidx[NPTS];
__device__ __nv_bfloat16 g_Mh[(size_t)MU*DD];    // UNnormalized rows hi/lo (gram)
__device__ __nv_bfloat16 g_Ml[(size_t)MU*DD];
__device__ __nv_bfloat16 g_A1h[(size_t)MU*DD];   // normalized rows (layer1 input)
__device__ __nv_bfloat16 g_W1h[(size_t)1024*DD]; // W1^T fused [1024 x 2048]
__device__ __nv_bfloat16 g_W2h[(size_t)512*NHID];
__device__ __nv_bfloat16 g_Wch[(size_t)HH2*HH2];
__device__ float g_U [(size_t)MU*1024];          // layer1 unique-row outputs [top|bot]
__device__ __nv_bfloat16 g_X1h[(size_t)MM*NHID];
__device__ float g_Z [(size_t)MM*NHID];          // layer2 outputs [top|bot] per row
__device__ __nv_bfloat16 g_X2h[(size_t)MM*HH2];
__device__ float g_Hc[(size_t)MM*HH2];
__device__ float g_G  [(size_t)BB*KK*KK];
__device__ float g_Adj[(size_t)BB*KK*KK];
__device__ int   g_row[MM];

// ---------------- helpers -----------------------------------------------------

__device__ __forceinline__ uint32_t smem_u32(const void* p) {
    uint32_t a;
    asm("{ .reg .u64 t; cvta.to.shared.u64 t, %1; cvt.u32.u64 %0, t; }"
        : "=r"(a) : "l"(p));
    return a;
}

#define CP_ASYNC16(saddr, gaddr) \
    asm volatile("cp.async.cg.shared.global [%0], [%1], 16;\n" \
                 :: "r"(saddr), "l"(gaddr))
#define CP_COMMIT() asm volatile("cp.async.commit_group;\n" ::: "memory")
#define CP_WAIT0()  asm volatile("cp.async.wait_group 0;\n" ::: "memory")
#define CP_WAIT1()  asm volatile("cp.async.wait_group 1;\n" ::: "memory")

#define LDMATRIX_X4(d0,d1,d2,d3, addr) \
    asm volatile("ldmatrix.sync.aligned.m8n8.x4.shared.b16 {%0,%1,%2,%3}, [%4];\n" \
        : "=r"(d0), "=r"(d1), "=r"(d2), "=r"(d3) : "r"(addr))

#define MMA16816(c, a, b0v, b1v) \
    asm volatile("mma.sync.aligned.m16n8k16.row.col.f32.bf16.bf16.f32 " \
        "{%0,%1,%2,%3}, {%4,%5,%6,%7}, {%8,%9}, {%0,%1,%2,%3};\n" \
        : "+f"((c)[0]), "+f"((c)[1]), "+f"((c)[2]), "+f"((c)[3]) \
        : "r"((a)[0]), "r"((a)[1]), "r"((a)[2]), "r"((a)[3]), \
          "r"(b0v), "r"(b1v))

// ---------------- cluster-mean pipeline (sorted, no big atomics) --------------

__global__ void k_zeroc()
{
    int i = blockIdx.x*blockDim.x + threadIdx.x;
    if (i < CC) g_icnt[i] = 0;
}

__global__ void k_count(const int* __restrict__ labels)
{
    int i = blockIdx.x*blockDim.x + threadIdx.x;
    if (i < NPTS) atomicAdd(&g_icnt[labels[i]], 1);
}

// exclusive prefix over CC counts, single block of 256
__global__ void k_scan()
{
    __shared__ int wsum[8];
    int t = threadIdx.x, lane = t & 31, w = t >> 5;
    int local[20];
    int s = 0;
    #pragma unroll
    for (int j = 0; j < 20; j++) {
        int c = t*20 + j;
        int v = (c < CC) ? g_icnt[c] : 0;
        local[j] = s;
        s += v;
    }
    int x = s;
    #pragma unroll
    for (int o = 1; o < 32; o <<= 1) {
        int y = __shfl_up_sync(0xFFFFFFFFu, x, o);
        if (lane >= o) x += y;
    }
    if (lane == 31) wsum[w] = x;
    __syncthreads();
    if (t == 0) {
        int acc = 0;
        #pragma unroll
        for (int i = 0; i < 8; i++) { int v = wsum[i]; wsum[i] = acc; acc += v; }
    }
    __syncthreads();
    int base = wsum[w] + (x - s);
    #pragma unroll
    for (int j = 0; j < 20; j++) {
        int c = t*20 + j;
        if (c < CC) { g_off[c] = base + local[j]; g_wptr[c] = base + local[j]; }
    }
}

__global__ void k_scatter(const int* __restrict__ labels)
{
    int i = blockIdx.x*blockDim.x + threadIdx.x;
    if (i < NPTS) {
        int pos = atomicAdd(&g_wptr[labels[i]], 1);
        g_sidx[pos] = i;
    }
}

// per-cluster mean: sum sorted member rows, write simm + bf16 hi/lo + normalized
__global__ __launch_bounds__(256)
void k_cmean(const float* __restrict__ feats, float* __restrict__ simm_out)
{
    __shared__ float red[256];
    int c = blockIdx.x, t = threadIdx.x;
    int n = g_icnt[c], base = g_off[c];
    float sum[8];
    #pragma unroll
    for (int j = 0; j < 8; j++) sum[j] = 0.f;
    for (int r = 0; r < n; r++) {
        const float* f = feats + (size_t)g_sidx[base + r]*DD;
        #pragma unroll
        for (int j = 0; j < 8; j++) sum[j] += f[t + j*256];
    }
    float invn = 1.0f / (float)max(n, 1);
    float m[8], ss = 0.f;
    #pragma unroll
    for (int j = 0; j < 8; j++) { m[j] = sum[j]*invn; ss += m[j]*m[j]; }
    red[t] = ss;
    __syncthreads();
    for (int o = 128; o > 0; o >>= 1) {
        if (t < o) red[t] += red[t + o];
        __syncthreads();
    }
    float s = red[0];
    if (t == 0) simm_out[c] = s;
    float inv = (s > 0.f) ? rsqrtf(s) : 0.f;
    size_t rb = (size_t)c*DD;
    #pragma unroll
    for (int j = 0; j < 8; j++) {
        int d = t + j*256;
        float v = m[j];
        __nv_bfloat16 h = __float2bfloat16(v);
        g_Mh[rb + d] = h;
        g_Ml[rb + d] = __float2bfloat16(v - __bfloat162float(h));
        g_A1h[rb + d] = __float2bfloat16(v*inv);
    }
}

// pivot rows: unnormalized hi/lo (gram) + normalized hi (layer1) at rows CC+b
__global__ void k_pivot(const float* __restrict__ feats,
                        const int* __restrict__ indexes)
{
    __shared__ float red[256];
    int b = blockIdx.x, t = threadIdx.x;
    const float* f = feats + (size_t)indexes[b]*DD;
    float vals[8];
    float ss = 0.f;
    #pragma unroll
    for (int j = 0; j < 8; j++) {
        float v = f[t + j*256];
        vals[j] = v;
        ss += v*v;
    }
    red[t] = ss;
    __syncthreads();
    for (int o = 128; o > 0; o >>= 1) {
        if (t < o) red[t] += red[t + o];
        __syncthreads();
    }
    float inv = rsqrtf(red[0]);
    size_t rb = (size_t)(CC + b)*DD;
    #pragma unroll
    for (int j = 0; j < 8; j++) {
        int d = t + j*256;
        float v = vals[j];
        __nv_bfloat16 h = __float2bfloat16(v);
        g_Mh[rb + d] = h;
        g_Ml[rb + d] = __float2bfloat16(v - __bfloat162float(h));
        g_A1h[rb + d] = __float2bfloat16(v*inv);
    }
}

__global__ void k_rowmap(const int* __restrict__ labels,
                         const int* __restrict__ knn)
{
    int i = blockIdx.x*blockDim.x + threadIdx.x;
    if (i >= MM) return;
    int b = i / KK, k = i % KK;
    g_row[i] = (k == 0) ? (CC + b) : labels[knn[i]];
}

// weight transpose + bf16 (hi only)
__global__ void k_convW(const float* __restrict__ W, int ldw, int Kd, int Nh,
                        __nv_bfloat16* __restrict__ dh)
{
    size_t i = (size_t)blockIdx.x*blockDim.x + threadIdx.x;
    int n = (int)(i / Kd), k = (int)(i % Kd);
    int col  = (n < Nh) ? n : n - Nh;
    int koff = (n < Nh) ? 0 : Kd;
    dh[i] = __float2bfloat16(W[(size_t)(koff + k)*ldw + col]);
}

// ---------------- gram via mma (bf16x3, gathered rows) ------------------------
// per block b: G[b] = F F^T, F rows = g_Mh/Ml[g_row[b*64+k]], 64x64xK=2048

#define GTS 72   // smem row stride (elems)

__global__ __launch_bounds__(256)
void k_gram_mma()
{
    __shared__ int rows[KK];
    __shared__ __align__(16) __nv_bfloat16 buf[2][2][KK*GTS];
    int b = blockIdx.x, t = threadIdx.x;
    int lane = t & 31, wid = t >> 5;
    int wr = wid & 3, wc = wid >> 2;

    if (t < KK) rows[t] = g_row[b*KK + t];
    __syncthreads();

    int g = lane >> 3, r = lane & 7;
    uint32_t a_off = (uint32_t)((wr*16 + ((g & 1) << 3) + r)*(GTS*2) + (((g >> 1) << 3) * 2));
    uint32_t b_off0 = (uint32_t)((wc*32 +      ((g >> 1) << 3) + r)*(GTS*2) + (((g & 1) << 3) * 2));
    uint32_t b_off1 = (uint32_t)((wc*32 + 16 + ((g >> 1) << 3) + r)*(GTS*2) + (((g & 1) << 3) * 2));

    float acc[4][4];
    #pragma unroll
    for (int ni = 0; ni < 4; ni++)
        #pragma unroll
        for (int q = 0; q < 4; q++) acc[ni][q] = 0.f;

    const int nch = DD >> 6;   // 32

    // prologue: chunks 0,1
    #pragma unroll
    for (int pre = 0; pre < 2; pre++) {
        int k0 = pre << 6;
        #pragma unroll
        for (int hl = 0; hl < 2; hl++) {
            const __nv_bfloat16* src = hl ? g_Ml : g_Mh;
            uint32_t sB = smem_u32(&buf[pre][hl][0]);
            #pragma unroll
            for (int i = 0; i < 2; i++) {
                int task = t + i*256;
                int row = task >> 3, c16 = task & 7;
                const __nv_bfloat16* ga = src + (size_t)rows[row]*DD + k0 + c16*8;
                CP_ASYNC16(sB + (uint32_t)(row*GTS*2 + c16*16), ga);
            }
        }
        CP_COMMIT();
    }

    for (int ch = 0; ch < nch; ch++) {
        if (ch == nch - 1) CP_WAIT0(); else CP_WAIT1();
        __syncthreads();
        uint32_t sH = smem_u32(&buf[ch & 1][0][0]);
        uint32_t sL = smem_u32(&buf[ch & 1][1][0]);

        #pragma unroll
        for (int ks = 0; ks < 4; ks++) {
            uint32_t kb = (uint32_t)(ks*32);
            uint32_t ah[4], al[4], bh[2][4], bl[2][4];
            LDMATRIX_X4(ah[0], ah[1], ah[2], ah[3], sH + a_off + kb);
            LDMATRIX_X4(al[0], al[1], al[2], al[3], sL + a_off + kb);
            LDMATRIX_X4(bh[0][0], bh[0][1], bh[0][2], bh[0][3], sH + b_off0 + kb);
            LDMATRIX_X4(bh[1][0], bh[1][1], bh[1][2], bh[1][3], sH + b_off1 + kb);
            LDMATRIX_X4(bl[0][0], bl[0][1], bl[0][2], bl[0][3], sL + b_off0 + kb);
            LDMATRIX_X4(bl[1][0], bl[1][1], bl[1][2], bl[1][3], sL + b_off1 + kb);
            #pragma unroll
            for (int ni = 0; ni < 4; ni++) {
                int nj = ni >> 1, h2 = (ni & 1)*2;
                MMA16816(acc[ni], ah, bh[nj][h2], bh[nj][h2+1]);
                MMA16816(acc[ni], ah, bl[nj][h2], bl[nj][h2+1]);
                MMA16816(acc[ni], al, bh[nj][h2], bh[nj][h2+1]);
            }
        }
        __syncthreads();
        if (ch + 2 < nch) {
            int k0 = (ch + 2) << 6;
            #pragma unroll
            for (int hl = 0; hl < 2; hl++) {
                const __nv_bfloat16* src = hl ? g_Ml : g_Mh;
                uint32_t sB = smem_u32(&buf[ch & 1][hl][0]);
                #pragma unroll
                for (int i = 0; i < 2; i++) {
                    int task = t + i*256;
                    int row = task >> 3, c16 = task & 7;
                    const __nv_bfloat16* ga = src + (size_t)rows[row]*DD + k0 + c16*8;
                    CP_ASYNC16(sB + (uint32_t)(row*GTS*2 + c16*16), ga);
                }
            }
            CP_COMMIT();
        }
    }

    float* Gb = g_G + (size_t)b*KK*KK;
    int rr0 = wr*16 + (lane >> 2);
    #pragma unroll
    for (int ni = 0; ni < 4; ni++) {
        int cc = wc*32 + ni*8 + (lane & 3)*2;
        float2 v0 = { acc[ni][0], acc[ni][1] };
        float2 v1 = { acc[ni][2], acc[ni][3] };
        *(float2*)&Gb[rr0*KK + cc]       = v0;
        *(float2*)&Gb[(rr0 + 8)*KK + cc] = v1;
    }
}

__global__ void k_buildA(const float* __restrict__ all_pred)
{
    __shared__ float red[KK];
    int b = blockIdx.x / KK;
    int k = blockIdx.x % KK;
    int j = threadIdx.x;
    float v = g_G[(size_t)b*KK*KK + k*KK + j] * expf(all_pred[(b*KK + j)*2 + 1]);
    red[j] = v;
    __syncthreads();
    for (int o = 32; o > 0; o >>= 1) {
        if (j < o) red[j] = fmaxf(red[j], red[j + o]);
        __syncthreads();
    }
    float mx = red[0];
    __syncthreads();
    float e = expf(v - mx);
    red[j] = e;
    __syncthreads();
    for (int o = 32; o > 0; o >>= 1) {
        if (j < o) red[j] += red[j + o];
        __syncthreads();
    }
    g_Adj[(size_t)b*KK*KK + k*KK + j] = e / red[0];
}

// ---------------- mma.sync pure-bf16 GEMM -------------------------------------
// C[M x Ncols] = A @ B^T ; 128x128 tile, 8 warps (32x64), K-chunk 64, dbl buffer

#define TSTRIDE 72
#define TILE_E  (128*TSTRIDE)
#define GEMM_SMEM (2*2*TILE_E*2)   // 73728 bytes

__global__ __launch_bounds__(256)
void k_mma_gemm(int Kd,
                const __nv_bfloat16* __restrict__ Ah,
                const __nv_bfloat16* __restrict__ Bh,
                float* __restrict__ C, int Ncols)
{
    extern __shared__ __nv_bfloat16 sm[];
    int t = threadIdx.x;
    int lane = t & 31, wid = t >> 5;
    int m0 = blockIdx.y*128, n0 = blockIdx.x*128;
    int wm = (wid & 3) * 32;
    int wn = (wid >> 2) * 64;

    uint32_t sbase = smem_u32(sm);
    int lrow = t >> 3;
    int c16  = t & 7;
    const __nv_bfloat16* gA = Ah + (size_t)m0*Kd;
    const __nv_bfloat16* gB = Bh + (size_t)n0*Kd;

    int nch = Kd >> 6;

    int g = lane >> 3, r = lane & 7;
    uint32_t a_row  = wm + ((g & 1) << 3) + r;
    uint32_t a_colB = (uint32_t)(((g >> 1) << 3) * 2);
    uint32_t b_row  = wn + ((g >> 1) << 3) + r;
    uint32_t b_colB = (uint32_t)(((g & 1) << 3) * 2);

    float acc[2][8][4];
    #pragma unroll
    for (int mi = 0; mi < 2; mi++)
        #pragma unroll
        for (int ni = 0; ni < 8; ni++)
            #pragma unroll
            for (int q = 0; q < 4; q++) acc[mi][ni][q] = 0.f;

    #pragma unroll
    for (int pre = 0; pre < 2; pre++) {
        uint32_t sb = sbase + (uint32_t)pre*(2*TILE_E*2);
        int k0 = pre << 6;
        #pragma unroll
        for (int i = 0; i < 4; i++) {
            int rr = lrow + i*32;
            size_t go = (size_t)rr*Kd + k0 + c16*8;
            uint32_t so = (uint32_t)(rr*TSTRIDE)*2 + (uint32_t)c16*16;
            CP_ASYNC16(sb + so, gA + go);
            CP_ASYNC16(sb + TILE_E*2 + so, gB + go);
        }
        CP_COMMIT();
    }

    for (int ch = 0; ch < nch; ch++) {
        if (ch == nch - 1) CP_WAIT0(); else CP_WAIT1();
        __syncthreads();

        uint32_t sb  = sbase + (uint32_t)(ch & 1)*(2*TILE_E*2);
        uint32_t sA = sb;
        uint32_t sB = sb + TILE_E*2;

        #pragma unroll
        for (int ks = 0; ks < 4; ks++) {
            uint32_t kb = (uint32_t)(ks*32);
            uint32_t ah[2][4];
            #pragma unroll
            for (int mi = 0; mi < 2; mi++) {
                uint32_t ra = (a_row + mi*16)*(TSTRIDE*2) + a_colB + kb;
                LDMATRIX_X4(ah[mi][0], ah[mi][1], ah[mi][2], ah[mi][3], sA + ra);
            }
            uint32_t bh[4][4];
            #pragma unroll
            for (int nj = 0; nj < 4; nj++) {
                uint32_t rb = (b_row + nj*16)*(TSTRIDE*2) + b_colB + kb;
                LDMATRIX_X4(bh[nj][0], bh[nj][1], bh[nj][2], bh[nj][3], sB + rb);
            }
            #pragma unroll
            for (int mi = 0; mi < 2; mi++)
                #pragma unroll
                for (int ni = 0; ni < 8; ni++) {
                    int nj = ni >> 1, h = (ni & 1) * 2;
                    MMA16816(acc[mi][ni], ah[mi], bh[nj][h], bh[nj][h+1]);
                }
        }
        __syncthreads();
        if (ch + 2 < nch) {
            uint32_t sb2 = sbase + (uint32_t)(ch & 1)*(2*TILE_E*2);
            int k0 = (ch + 2) << 6;
            #pragma unroll
            for (int i = 0; i < 4; i++) {
                int rr = lrow + i*32;
                size_t go = (size_t)rr*Kd + k0 + c16*8;
                uint32_t so = (uint32_t)(rr*TSTRIDE)*2 + (uint32_t)c16*16;
                CP_ASYNC16(sb2 + so, gA + go);
                CP_ASYNC16(sb2 + TILE_E*2 + so, gB + go);
            }
            CP_COMMIT();
        }
    }

    #pragma unroll
    for (int mi = 0; mi < 2; mi++) {
        int rr0 = m0 + wm + mi*16 + (lane >> 2);
        #pragma unroll
        for (int ni = 0; ni < 8; ni++) {
            int cc = n0 + wn + ni*8 + (lane & 3)*2;
            float2 v0 = { acc[mi][ni][0], acc[mi][ni][1] };
            float2 v1 = { acc[mi][ni][2], acc[mi][ni][3] };
            *(float2*)&C[(size_t)rr0*Ncols + cc]       = v0;
            *(float2*)&C[(size_t)(rr0 + 8)*Ncols + cc] = v1;
        }
    }
}

// ---------------- combines ----------------------------------------------------

__global__ __launch_bounds__(256)
void k_combine1(const float* __restrict__ bias)
{
    __shared__ float As[KK][KK];
    __shared__ float Bs[32][128];
    __shared__ int   rows[KK];
    int b    = blockIdx.y;
    int col0 = blockIdx.x * 128;
    int t = threadIdx.x;
    int tx = t & 15, ty = t >> 4;

    const float* Ab = g_Adj + (size_t)b*KK*KK;
    for (int idx = t; idx < KK*KK; idx += 256)
        As[idx >> 6][idx & 63] = Ab[idx];
    if (t < KK) rows[t] = g_row[b*KK + t];
    __syncthreads();

    int piv = CC + b;
    int cc  = col0 + tx*8;
    const float* Up = g_U + (size_t)piv*1024;
    float4 upa = *(const float4*)(Up + cc);
    float4 upb = *(const float4*)(Up + cc + 4);
    float4 uba = *(const float4*)(Up + 512 + cc);
    float4 ubb = *(const float4*)(Up + 512 + cc + 4);
    float up[8] = {upa.x,upa.y,upa.z,upa.w,upb.x,upb.y,upb.z,upb.w};
    float ub[8] = {uba.x,uba.y,uba.z,uba.w,ubb.x,ubb.y,ubb.z,ubb.w};

    float acc[4][8];
    #pragma unroll
    for (int i = 0; i < 4; i++)
        #pragma unroll
        for (int c = 0; c < 8; c++) acc[i][c] = 0.f;

    for (int jt = 0; jt < KK; jt += 32) {
        #pragma unroll
        for (int i = 0; i < 4; i++) {
            int idx = t + i*256;
            int j = idx >> 5, c4 = idx & 31;
            *(float4*)&Bs[j][c4*4] =
                *(const float4*)(g_U + (size_t)rows[jt + j]*1024 + 512 + col0 + c4*4);
        }
        __syncthreads();
        #pragma unroll 4
        for (int j = 0; j < 32; j++) {
            float a[4];
            #pragma unroll
            for (int i = 0; i < 4; i++) a[i] = As[ty*4 + i][jt + j];
            float4 b0 = *(const float4*)&Bs[j][tx*8];
            float4 b1 = *(const float4*)&Bs[j][tx*8 + 4];
            float bf[8] = {b0.x,b0.y,b0.z,b0.w,b1.x,b1.y,b1.z,b1.w};
            #pragma unroll
            for (int i = 0; i < 4; i++)
                #pragma unroll
                for (int c = 0; c < 8; c++)
                    acc[i][c] = fmaf(a[i], bf[c], acc[i][c]);
        }
        __syncthreads();
    }
    #pragma unroll
    for (int i = 0; i < 4; i++) {
        int k = ty*4 + i;
        size_t m = (size_t)(b*KK + k);
        const float* ut = g_U + (size_t)rows[k]*1024 + cc;
        float4 t0 = *(const float4*)ut;
        float4 t1 = *(const float4*)(ut + 4);
        float uv[8] = {t0.x,t0.y,t0.z,t0.w,t1.x,t1.y,t1.z,t1.w};
        #pragma unroll
        for (int c = 0; c < 8; c++) {
            float v = acc[i][c] + uv[c] - up[c] - ub[c] + bias[cc + c];
            g_X1h[m*NHID + cc + c] = __float2bfloat16(fmaxf(v, 0.f));
        }
    }
}

__global__ __launch_bounds__(256)
void k_combine2(const float* __restrict__ bias)
{
    __shared__ float As[KK][KK];
    __shared__ float Bs[32][128];
    int b    = blockIdx.y;
    int col0 = blockIdx.x * 128;
    int t = threadIdx.x;
    int tx = t & 15, ty = t >> 4;

    const float* Ab = g_Adj + (size_t)b*KK*KK;
    for (int idx = t; idx < KK*KK; idx += 256)
        As[idx >> 6][idx & 63] = Ab[idx];

    float acc[4][8];
    #pragma unroll
    for (int i = 0; i < 4; i++)
        #pragma unroll
        for (int c = 0; c < 8; c++) acc[i][c] = 0.f;

    for (int jt = 0; jt < KK; jt += 32) {
        __syncthreads();
        #pragma unroll
        for (int i = 0; i < 4; i++) {
            int idx = t + i*256;
            int j = idx >> 5, c4 = idx & 31;
            *(float4*)&Bs[j][c4*4] =
                *(const float4*)(g_Z + (size_t)(b*KK + jt + j)*512 + 256 + col0 + c4*4);
        }
        __syncthreads();
        #pragma unroll 4
        for (int j = 0; j < 32; j++) {
            float a[4];
            #pragma unroll
            for (int i = 0; i < 4; i++) a[i] = As[ty*4 + i][jt + j];
            float4 b0 = *(const float4*)&Bs[j][tx*8];
            float4 b1 = *(const float4*)&Bs[j][tx*8 + 4];
            float bf[8] = {b0.x,b0.y,b0.z,b0.w,b1.x,b1.y,b1.z,b1.w};
            #pragma unroll
            for (int i = 0; i < 4; i++)
                #pragma unroll
                for (int c = 0; c < 8; c++)
                    acc[i][c] = fmaf(a[i], bf[c], acc[i][c]);
        }
    }
    #pragma unroll
    for (int i = 0; i < 4; i++) {
        size_t m = (size_t)(b*KK + ty*4 + i);
        #pragma unroll
        for (int c = 0; c < 8; c++) {
            int cc = col0 + tx*8 + c;
            float v = acc[i][c] + g_Z[m*512 + cc] + bias[cc];
            g_X2h[m*HH2 + cc] = __float2bfloat16(fmaxf(v, 0.f));
        }
    }
}

__global__ void k_head(const float* __restrict__ bc1,
                       const float* __restrict__ prelu_a,
                       const float* __restrict__ Wc2,
                       const float* __restrict__ bc2,
                       float* __restrict__ pred_out)
{
    __shared__ float s0[256], s1[256];
    int m = blockIdx.x;
    int c = threadIdx.x;
    float h = g_Hc[(size_t)m*HH2 + c] + bc1[c];
    h = (h >= 0.f) ? h : prelu_a[c]*h;
    s0[c] = h * Wc2[2*c];
    s1[c] = h * Wc2[2*c + 1];
    __syncthreads();
    for (int o = 128; o > 0; o >>= 1) {
        if (c < o) { s0[c] += s0[c + o]; s1[c] += s1[c + o]; }
        __syncthreads();
    }
    if (c == 0) {
        float l0 = s0[0] + bc2[0];
        float l1 = s1[0] + bc2[1];
        float mx = fmaxf(l0, l1);
        float e0 = expf(l0 - mx), e1 = expf(l1 - mx);
        float inv = 1.0f / (e0 + e1);
        pred_out[2*m]     = e0*inv;
        pred_out[2*m + 1] = e1*inv;
    }
}

// ---------------- launch -----------------------------------------------------

extern "C" void kernel_launch(void* const* d_in, const int* in_sizes, int n_in,
                              void* d_out, int out_size)
{
    const int*   indexes  = (const int*)  d_in[0];
    const float* features = (const float*)d_in[1];
    const int*   labels   = (const int*)  d_in[2];
    const int*   knn      = (const int*)  d_in[5];
    const float* all_pred = (const float*)d_in[6];
    const float* W1  = (const float*)d_in[7];
    const float* b1  = (const float*)d_in[8];
    const float* W2  = (const float*)d_in[9];
    const float* b2  = (const float*)d_in[10];
    const float* Wc1 = (const float*)d_in[11];
    const float* bc1 = (const float*)d_in[12];
    const float* pa  = (const float*)d_in[13];
    const float* Wc2 = (const float*)d_in[14];
    const float* bc2 = (const float*)d_in[15];

    float* out = (float*)d_out;
    float* pred_out = out;
    float* simm_out = out + (size_t)MM*2;

    cudaFuncSetAttribute(k_mma_gemm, cudaFuncAttributeMaxDynamicSharedMemorySize,
                         GEMM_SMEM);

    __nv_bfloat16 *pA1h,*pW1h,*pW2h,*pWch,*pX1h,*pX2h;
    float *pU,*pZ,*pHc;
    cudaGetSymbolAddress((void**)&pA1h, g_A1h);
    cudaGetSymbolAddress((void**)&pW1h, g_W1h);
    cudaGetSymbolAddress((void**)&pW2h, g_W2h);
    cudaGetSymbolAddress((void**)&pWch, g_Wch);
    cudaGetSymbolAddress((void**)&pX1h, g_X1h);
    cudaGetSymbolAddress((void**)&pX2h, g_X2h);
    cudaGetSymbolAddress((void**)&pU,  g_U);
    cudaGetSymbolAddress((void**)&pZ,  g_Z);
    cudaGetSymbolAddress((void**)&pHc, g_Hc);

    // weight transposes (hi only)
    k_convW<<<(1024u*DD)/256, 256>>>(W1, NHID, DD, NHID, pW1h);
    k_convW<<<(512u*NHID)/256, 256>>>(W2, HH2, NHID, HH2, pW2h);
    k_convW<<<(HH2*HH2)/256, 256>>>(Wc1, HH2, HH2, HH2, pWch);

    // sorted cluster means + simm + bf16 rows
    k_zeroc<<<(CC + 255)/256, 256>>>();
    k_count<<<(NPTS + 255)/256, 256>>>(labels);
    k_scan<<<1, 256>>>();
    k_scatter<<<(NPTS + 255)/256, 256>>>(labels);
    k_cmean<<<CC, 256>>>(features, simm_out);
    k_pivot<<<BB, 256>>>(features, indexes);
    k_rowmap<<<(MM + 255)/256, 256>>>(labels, knn);

    // per-batch gram (tensor, bf16x3) + adjacency
    k_gram_mma<<<BB, 256>>>();
    k_buildA<<<BB*KK, KK>>>(all_pred);

    // layer 1: U = A1 @ W1t^T  (unique rows, fused top|bot N=1024)
    k_mma_gemm<<<dim3(1024/128, MU/128), 256, GEMM_SMEM>>>(DD, pA1h, pW1h, pU, 1024);
    k_combine1<<<dim3(NHID/128, BB), 256>>>(b1);

    // layer 2: Z = X1 @ W2t^T  (fused top|bot N=512)
    k_mma_gemm<<<dim3(512/128, MM/128), 256, GEMM_SMEM>>>(NHID, pX1h, pW2h, pZ, 512);
    k_combine2<<<dim3(HH2/128, BB), 256>>>(b2);

    // classifier: Hc = X2 @ Wc1t^T
    k_mma_gemm<<<dim3(HH2/128, MM/128), 256, GEMM_SMEM>>>(HH2, pX2h, pWch, pHc, 256);
    k_head<<<MM, 256>>>(bc1, pa, Wc2, bc2, pred_out);

    (void)in_sizes; (void)n_in; (void)out_size;
}

// round 7
// speedup vs baseline: 6.6082x; 1.1287x over previous
#include <cuda_runtime.h>
#include <cuda_bf16.h>
#include <math.h>
#include <stdint.h>

#define BB   256
#define KK   64
#define DD   2048
#define NPTS 50000
#define CC   5000
#define NHID 512
#define HH2  256
#define MM   (BB*KK)        // 16384
#define MU   5376           // padded unique rows: 5000 clusters + 256 pivots + pad

// ---------------- scratch (device globals; no allocations allowed) ----------
__device__ int   g_icnt[CC];
__device__ int   g_off[CC];
__device__ int   g_wptr[CC];
__device__ int   g_sidx[NPTS];
__device__ __nv_bfloat16 g_Mh[(size_t)MU*DD];    // UNnormalized rows hi/lo (gram)
__device__ __nv_bfloat16 g_Ml[(size_t)MU*DD];
__device__ __nv_bfloat16 g_A1h[(size_t)MU*DD];   // normalized rows (layer1 input)
__device__ __nv_bfloat16 g_W1h[(size_t)1024*DD]; // W1^T fused [1024 x 2048]
__device__ __nv_bfloat16 g_W2h[(size_t)512*NHID];
__device__ __nv_bfloat16 g_Wch[(size_t)HH2*HH2];
__device__ float g_U [(size_t)MU*1024];          // layer1 unique-row outputs [top|bot]
__device__ __nv_bfloat16 g_X1h[(size_t)MM*NHID];
__device__ float g_Z [(size_t)MM*NHID];          // layer2 outputs [top|bot] per row
__device__ __nv_bfloat16 g_X2h[(size_t)MM*HH2];
__device__ float g_Hc[(size_t)MM*HH2];
__device__ float g_G  [(size_t)BB*KK*KK];
__device__ float g_Adj[(size_t)BB*KK*KK];
__device__ int   g_row[MM];

// ---------------- streams/events for graph-level parallelism -----------------
// Created at static init (pre-main, outside graph capture and mem checkpoints).
static cudaStream_t g_s1, g_s2;
static cudaEvent_t  g_evF1, g_evF2, g_evW, g_evG;
static int g_async_init = [](){
    cudaStreamCreateWithFlags(&g_s1, cudaStreamNonBlocking);
    cudaStreamCreateWithFlags(&g_s2, cudaStreamNonBlocking);
    cudaEventCreateWithFlags(&g_evF1, cudaEventDisableTiming);
    cudaEventCreateWithFlags(&g_evF2, cudaEventDisableTiming);
    cudaEventCreateWithFlags(&g_evW,  cudaEventDisableTiming);
    cudaEventCreateWithFlags(&g_evG,  cudaEventDisableTiming);
    return 0;
}();

// ---------------- helpers -----------------------------------------------------

__device__ __forceinline__ uint32_t smem_u32(const void* p) {
    uint32_t a;
    asm("{ .reg .u64 t; cvta.to.shared.u64 t, %1; cvt.u32.u64 %0, t; }"
        : "=r"(a) : "l"(p));
    return a;
}

#define CP_ASYNC16(saddr, gaddr) \
    asm volatile("cp.async.cg.shared.global [%0], [%1], 16;\n" \
                 :: "r"(saddr), "l"(gaddr))
#define CP_COMMIT() asm volatile("cp.async.commit_group;\n" ::: "memory")
#define CP_WAIT0()  asm volatile("cp.async.wait_group 0;\n" ::: "memory")
#define CP_WAIT1()  asm volatile("cp.async.wait_group 1;\n" ::: "memory")

#define LDMATRIX_X4(d0,d1,d2,d3, addr) \
    asm volatile("ldmatrix.sync.aligned.m8n8.x4.shared.b16 {%0,%1,%2,%3}, [%4];\n" \
        : "=r"(d0), "=r"(d1), "=r"(d2), "=r"(d3) : "r"(addr))

#define MMA16816(c, a, b0v, b1v) \
    asm volatile("mma.sync.aligned.m16n8k16.row.col.f32.bf16.bf16.f32 " \
        "{%0,%1,%2,%3}, {%4,%5,%6,%7}, {%8,%9}, {%0,%1,%2,%3};\n" \
        : "+f"((c)[0]), "+f"((c)[1]), "+f"((c)[2]), "+f"((c)[3]) \
        : "r"((a)[0]), "r"((a)[1]), "r"((a)[2]), "r"((a)[3]), \
          "r"(b0v), "r"(b1v))

// ---------------- cluster-mean pipeline (sorted, no big atomics) --------------

__global__ void k_zeroc()
{
    int i = blockIdx.x*blockDim.x + threadIdx.x;
    if (i < CC) g_icnt[i] = 0;
}

__global__ void k_count(const int* __restrict__ labels)
{
    int i = blockIdx.x*blockDim.x + threadIdx.x;
    if (i < NPTS) atomicAdd(&g_icnt[labels[i]], 1);
}

// exclusive prefix over CC counts, single block of 256
__global__ void k_scan()
{
    __shared__ int wsum[8];
    int t = threadIdx.x, lane = t & 31, w = t >> 5;
    int local[20];
    int s = 0;
    #pragma unroll
    for (int j = 0; j < 20; j++) {
        int c = t*20 + j;
        int v = (c < CC) ? g_icnt[c] : 0;
        local[j] = s;
        s += v;
    }
    int x = s;
    #pragma unroll
    for (int o = 1; o < 32; o <<= 1) {
        int y = __shfl_up_sync(0xFFFFFFFFu, x, o);
        if (lane >= o) x += y;
    }
    if (lane == 31) wsum[w] = x;
    __syncthreads();
    if (t == 0) {
        int acc = 0;
        #pragma unroll
        for (int i = 0; i < 8; i++) { int v = wsum[i]; wsum[i] = acc; acc += v; }
    }
    __syncthreads();
    int base = wsum[w] + (x - s);
    #pragma unroll
    for (int j = 0; j < 20; j++) {
        int c = t*20 + j;
        if (c < CC) { g_off[c] = base + local[j]; g_wptr[c] = base + local[j]; }
    }
}

__global__ void k_scatter(const int* __restrict__ labels)
{
    int i = blockIdx.x*blockDim.x + threadIdx.x;
    if (i < NPTS) {
        int pos = atomicAdd(&g_wptr[labels[i]], 1);
        g_sidx[pos] = i;
    }
}

// rows [0,CC): cluster mean; rows [CC,CC+BB): pivot features.
// writes simm (clusters only) + unnormalized bf16 hi/lo + normalized bf16.
__global__ __launch_bounds__(256)
void k_cmean(const float* __restrict__ feats,
             const int* __restrict__ indexes,
             float* __restrict__ simm_out)
{
    __shared__ float red[256];
    int c = blockIdx.x, t = threadIdx.x;
    float4 s0 = {0,0,0,0}, s1 = {0,0,0,0};
    float invn;
    if (c < CC) {
        int n = g_icnt[c], base = g_off[c];
        for (int r = 0; r < n; r++) {
            const float4* f = (const float4*)(feats + (size_t)g_sidx[base + r]*DD);
            float4 a = f[t], b = f[t + 256];
            s0.x += a.x; s0.y += a.y; s0.z += a.z; s0.w += a.w;
            s1.x += b.x; s1.y += b.y; s1.z += b.z; s1.w += b.w;
        }
        invn = 1.0f / (float)max(n, 1);
    } else {
        const float4* f = (const float4*)(feats + (size_t)indexes[c - CC]*DD);
        s0 = f[t]; s1 = f[t + 256];
        invn = 1.0f;
    }
    float m[8] = { s0.x*invn, s0.y*invn, s0.z*invn, s0.w*invn,
                   s1.x*invn, s1.y*invn, s1.z*invn, s1.w*invn };
    float ss = 0.f;
    #pragma unroll
    for (int j = 0; j < 8; j++) ss += m[j]*m[j];
    red[t] = ss;
    __syncthreads();
    for (int o = 128; o > 0; o >>= 1) {
        if (t < o) red[t] += red[t + o];
        __syncthreads();
    }
    float s = red[0];
    if (c < CC && t == 0) simm_out[c] = s;
    float inv = (s > 0.f) ? rsqrtf(s) : 0.f;
    size_t rb = (size_t)c*DD;
    #pragma unroll
    for (int j = 0; j < 8; j++) {
        int d = (j < 4) ? (t*4 + j) : (1024 + t*4 + (j - 4));
        float v = m[j];
        __nv_bfloat16 h = __float2bfloat16(v);
        g_Mh[rb + d] = h;
        g_Ml[rb + d] = __float2bfloat16(v - __bfloat162float(h));
        g_A1h[rb + d] = __float2bfloat16(v*inv);
    }
}

__global__ void k_rowmap(const int* __restrict__ labels,
                         const int* __restrict__ knn)
{
    int i = blockIdx.x*blockDim.x + threadIdx.x;
    if (i >= MM) return;
    int b = i / KK, k = i % KK;
    g_row[i] = (k == 0) ? (CC + b) : labels[knn[i]];
}

// weight transpose + bf16 (hi only)
__global__ void k_convW(const float* __restrict__ W, int ldw, int Kd, int Nh,
                        __nv_bfloat16* __restrict__ dh)
{
    size_t i = (size_t)blockIdx.x*blockDim.x + threadIdx.x;
    int n = (int)(i / Kd), k = (int)(i % Kd);
    int col  = (n < Nh) ? n : n - Nh;
    int koff = (n < Nh) ? 0 : Kd;
    dh[i] = __float2bfloat16(W[(size_t)(koff + k)*ldw + col]);
}

// ---------------- gram via mma (bf16x3, gathered rows) ------------------------

#define GTS 72   // smem row stride (elems)

__global__ __launch_bounds__(256)
void k_gram_mma()
{
    __shared__ int rows[KK];
    __shared__ __align__(16) __nv_bfloat16 buf[2][2][KK*GTS];
    int b = blockIdx.x, t = threadIdx.x;
    int lane = t & 31, wid = t >> 5;
    int wr = wid & 3, wc = wid >> 2;

    if (t < KK) rows[t] = g_row[b*KK + t];
    __syncthreads();

    int g = lane >> 3, r = lane & 7;
    uint32_t a_off = (uint32_t)((wr*16 + ((g & 1) << 3) + r)*(GTS*2) + (((g >> 1) << 3) * 2));
    uint32_t b_off0 = (uint32_t)((wc*32 +      ((g >> 1) << 3) + r)*(GTS*2) + (((g & 1) << 3) * 2));
    uint32_t b_off1 = (uint32_t)((wc*32 + 16 + ((g >> 1) << 3) + r)*(GTS*2) + (((g & 1) << 3) * 2));

    float acc[4][4];
    #pragma unroll
    for (int ni = 0; ni < 4; ni++)
        #pragma unroll
        for (int q = 0; q < 4; q++) acc[ni][q] = 0.f;

    const int nch = DD >> 6;   // 32

    #pragma unroll
    for (int pre = 0; pre < 2; pre++) {
        int k0 = pre << 6;
        #pragma unroll
        for (int hl = 0; hl < 2; hl++) {
            const __nv_bfloat16* src = hl ? g_Ml : g_Mh;
            uint32_t sB = smem_u32(&buf[pre][hl][0]);
            #pragma unroll
            for (int i = 0; i < 2; i++) {
                int task = t + i*256;
                int row = task >> 3, c16 = task & 7;
                const __nv_bfloat16* ga = src + (size_t)rows[row]*DD + k0 + c16*8;
                CP_ASYNC16(sB + (uint32_t)(row*GTS*2 + c16*16), ga);
            }
        }
        CP_COMMIT();
    }

    for (int ch = 0; ch < nch; ch++) {
        if (ch == nch - 1) CP_WAIT0(); else CP_WAIT1();
        __syncthreads();
        uint32_t sH = smem_u32(&buf[ch & 1][0][0]);
        uint32_t sL = smem_u32(&buf[ch & 1][1][0]);

        #pragma unroll
        for (int ks = 0; ks < 4; ks++) {
            uint32_t kb = (uint32_t)(ks*32);
            uint32_t ah[4], al[4], bh[2][4], bl[2][4];
            LDMATRIX_X4(ah[0], ah[1], ah[2], ah[3], sH + a_off + kb);
            LDMATRIX_X4(al[0], al[1], al[2], al[3], sL + a_off + kb);
            LDMATRIX_X4(bh[0][0], bh[0][1], bh[0][2], bh[0][3], sH + b_off0 + kb);
            LDMATRIX_X4(bh[1][0], bh[1][1], bh[1][2], bh[1][3], sH + b_off1 + kb);
            LDMATRIX_X4(bl[0][0], bl[0][1], bl[0][2], bl[0][3], sL + b_off0 + kb);
            LDMATRIX_X4(bl[1][0], bl[1][1], bl[1][2], bl[1][3], sL + b_off1 + kb);
            #pragma unroll
            for (int ni = 0; ni < 4; ni++) {
                int nj = ni >> 1, h2 = (ni & 1)*2;
                MMA16816(acc[ni], ah, bh[nj][h2], bh[nj][h2+1]);
                MMA16816(acc[ni], ah, bl[nj][h2], bl[nj][h2+1]);
                MMA16816(acc[ni], al, bh[nj][h2], bh[nj][h2+1]);
            }
        }
        __syncthreads();
        if (ch + 2 < nch) {
            int k0 = (ch + 2) << 6;
            #pragma unroll
            for (int hl = 0; hl < 2; hl++) {
                const __nv_bfloat16* src = hl ? g_Ml : g_Mh;
                uint32_t sB = smem_u32(&buf[ch & 1][hl][0]);
                #pragma unroll
                for (int i = 0; i < 2; i++) {
                    int task = t + i*256;
                    int row = task >> 3, c16 = task & 7;
                    const __nv_bfloat16* ga = src + (size_t)rows[row]*DD + k0 + c16*8;
                    CP_ASYNC16(sB + (uint32_t)(row*GTS*2 + c16*16), ga);
                }
            }
            CP_COMMIT();
        }
    }

    float* Gb = g_G + (size_t)b*KK*KK;
    int rr0 = wr*16 + (lane >> 2);
    #pragma unroll
    for (int ni = 0; ni < 4; ni++) {
        int cc = wc*32 + ni*8 + (lane & 3)*2;
        float2 v0 = { acc[ni][0], acc[ni][1] };
        float2 v1 = { acc[ni][2], acc[ni][3] };
        *(float2*)&Gb[rr0*KK + cc]       = v0;
        *(float2*)&Gb[(rr0 + 8)*KK + cc] = v1;
    }
}

__global__ void k_buildA(const float* __restrict__ all_pred)
{
    __shared__ float red[KK];
    int b = blockIdx.x / KK;
    int k = blockIdx.x % KK;
    int j = threadIdx.x;
    float v = g_G[(size_t)b*KK*KK + k*KK + j] * expf(all_pred[(b*KK + j)*2 + 1]);
    red[j] = v;
    __syncthreads();
    for (int o = 32; o > 0; o >>= 1) {
        if (j < o) red[j] = fmaxf(red[j], red[j + o]);
        __syncthreads();
    }
    float mx = red[0];
    __syncthreads();
    float e = expf(v - mx);
    red[j] = e;
    __syncthreads();
    for (int o = 32; o > 0; o >>= 1) {
        if (j < o) red[j] += red[j + o];
        __syncthreads();
    }
    g_Adj[(size_t)b*KK*KK + k*KK + j] = e / red[0];
}

// ---------------- mma.sync pure-bf16 GEMM -------------------------------------

#define TSTRIDE 72
#define TILE_E  (128*TSTRIDE)
#define GEMM_SMEM (2*2*TILE_E*2)   // 73728 bytes

__global__ __launch_bounds__(256)
void k_mma_gemm(int Kd,
                const __nv_bfloat16* __restrict__ Ah,
                const __nv_bfloat16* __restrict__ Bh,
                float* __restrict__ C, int Ncols)
{
    extern __shared__ __nv_bfloat16 sm[];
    int t = threadIdx.x;
    int lane = t & 31, wid = t >> 5;
    int m0 = blockIdx.y*128, n0 = blockIdx.x*128;
    int wm = (wid & 3) * 32;
    int wn = (wid >> 2) * 64;

    uint32_t sbase = smem_u32(sm);
    int lrow = t >> 3;
    int c16  = t & 7;
    const __nv_bfloat16* gA = Ah + (size_t)m0*Kd;
    const __nv_bfloat16* gB = Bh + (size_t)n0*Kd;

    int nch = Kd >> 6;

    int g = lane >> 3, r = lane & 7;
    uint32_t a_row  = wm + ((g & 1) << 3) + r;
    uint32_t a_colB = (uint32_t)(((g >> 1) << 3) * 2);
    uint32_t b_row  = wn + ((g >> 1) << 3) + r;
    uint32_t b_colB = (uint32_t)(((g & 1) << 3) * 2);

    float acc[2][8][4];
    #pragma unroll
    for (int mi = 0; mi < 2; mi++)
        #pragma unroll
        for (int ni = 0; ni < 8; ni++)
            #pragma unroll
            for (int q = 0; q < 4; q++) acc[mi][ni][q] = 0.f;

    #pragma unroll
    for (int pre = 0; pre < 2; pre++) {
        uint32_t sb = sbase + (uint32_t)pre*(2*TILE_E*2);
        int k0 = pre << 6;
        #pragma unroll
        for (int i = 0; i < 4; i++) {
            int rr = lrow + i*32;
            size_t go = (size_t)rr*Kd + k0 + c16*8;
            uint32_t so = (uint32_t)(rr*TSTRIDE)*2 + (uint32_t)c16*16;
            CP_ASYNC16(sb + so, gA + go);
            CP_ASYNC16(sb + TILE_E*2 + so, gB + go);
        }
        CP_COMMIT();
    }

    for (int ch = 0; ch < nch; ch++) {
        if (ch == nch - 1) CP_WAIT0(); else CP_WAIT1();
        __syncthreads();

        uint32_t sb  = sbase + (uint32_t)(ch & 1)*(2*TILE_E*2);
        uint32_t sA = sb;
        uint32_t sB = sb + TILE_E*2;

        #pragma unroll
        for (int ks = 0; ks < 4; ks++) {
            uint32_t kb = (uint32_t)(ks*32);
            uint32_t ah[2][4];
            #pragma unroll
            for (int mi = 0; mi < 2; mi++) {
                uint32_t ra = (a_row + mi*16)*(TSTRIDE*2) + a_colB + kb;
                LDMATRIX_X4(ah[mi][0], ah[mi][1], ah[mi][2], ah[mi][3], sA + ra);
            }
            uint32_t bh[4][4];
            #pragma unroll
            for (int nj = 0; nj < 4; nj++) {
                uint32_t rb = (b_row + nj*16)*(TSTRIDE*2) + b_colB + kb;
                LDMATRIX_X4(bh[nj][0], bh[nj][1], bh[nj][2], bh[nj][3], sB + rb);
            }
            #pragma unroll
            for (int mi = 0; mi < 2; mi++)
                #pragma unroll
                for (int ni = 0; ni < 8; ni++) {
                    int nj = ni >> 1, h = (ni & 1) * 2;
                    MMA16816(acc[mi][ni], ah[mi], bh[nj][h], bh[nj][h+1]);
                }
        }
        __syncthreads();
        if (ch + 2 < nch) {
            uint32_t sb2 = sbase + (uint32_t)(ch & 1)*(2*TILE_E*2);
            int k0 = (ch + 2) << 6;
            #pragma unroll
            for (int i = 0; i < 4; i++) {
                int rr = lrow + i*32;
                size_t go = (size_t)rr*Kd + k0 + c16*8;
                uint32_t so = (uint32_t)(rr*TSTRIDE)*2 + (uint32_t)c16*16;
                CP_ASYNC16(sb2 + so, gA + go);
                CP_ASYNC16(sb2 + TILE_E*2 + so, gB + go);
            }
            CP_COMMIT();
        }
    }

    #pragma unroll
    for (int mi = 0; mi < 2; mi++) {
        int rr0 = m0 + wm + mi*16 + (lane >> 2);
        #pragma unroll
        for (int ni = 0; ni < 8; ni++) {
            int cc = n0 + wn + ni*8 + (lane & 3)*2;
            float2 v0 = { acc[mi][ni][0], acc[mi][ni][1] };
            float2 v1 = { acc[mi][ni][2], acc[mi][ni][3] };
            *(float2*)&C[(size_t)rr0*Ncols + cc]       = v0;
            *(float2*)&C[(size_t)(rr0 + 8)*Ncols + cc] = v1;
        }
    }
}

// ---------------- combines ----------------------------------------------------

__global__ __launch_bounds__(256)
void k_combine1(const float* __restrict__ bias)
{
    __shared__ float As[KK][KK];
    __shared__ float Bs[32][128];
    __shared__ int   rows[KK];
    int b    = blockIdx.y;
    int col0 = blockIdx.x * 128;
    int t = threadIdx.x;
    int tx = t & 15, ty = t >> 4;

    const float* Ab = g_Adj + (size_t)b*KK*KK;
    for (int idx = t; idx < KK*KK; idx += 256)
        As[idx >> 6][idx & 63] = Ab[idx];
    if (t < KK) rows[t] = g_row[b*KK + t];
    __syncthreads();

    int piv = CC + b;
    int cc  = col0 + tx*8;
    const float* Up = g_U + (size_t)piv*1024;
    float4 upa = *(const float4*)(Up + cc);
    float4 upb = *(const float4*)(Up + cc + 4);
    float4 uba = *(const float4*)(Up + 512 + cc);
    float4 ubb = *(const float4*)(Up + 512 + cc + 4);
    float up[8] = {upa.x,upa.y,upa.z,upa.w,upb.x,upb.y,upb.z,upb.w};
    float ub[8] = {uba.x,uba.y,uba.z,uba.w,ubb.x,ubb.y,ubb.z,ubb.w};

    float acc[4][8];
    #pragma unroll
    for (int i = 0; i < 4; i++)
        #pragma unroll
        for (int c = 0; c < 8; c++) acc[i][c] = 0.f;

    for (int jt = 0; jt < KK; jt += 32) {
        #pragma unroll
        for (int i = 0; i < 4; i++) {
            int idx = t + i*256;
            int j = idx >> 5, c4 = idx & 31;
            *(float4*)&Bs[j][c4*4] =
                *(const float4*)(g_U + (size_t)rows[jt + j]*1024 + 512 + col0 + c4*4);
        }
        __syncthreads();
        #pragma unroll 4
        for (int j = 0; j < 32; j++) {
            float a[4];
            #pragma unroll
            for (int i = 0; i < 4; i++) a[i] = As[ty*4 + i][jt + j];
            float4 b0 = *(const float4*)&Bs[j][tx*8];
            float4 b1 = *(const float4*)&Bs[j][tx*8 + 4];
            float bf[8] = {b0.x,b0.y,b0.z,b0.w,b1.x,b1.y,b1.z,b1.w};
            #pragma unroll
            for (int i = 0; i < 4; i++)
                #pragma unroll
                for (int c = 0; c < 8; c++)
                    acc[i][c] = fmaf(a[i], bf[c], acc[i][c]);
        }
        __syncthreads();
    }
    #pragma unroll
    for (int i = 0; i < 4; i++) {
        int k = ty*4 + i;
        size_t m = (size_t)(b*KK + k);
        const float* ut = g_U + (size_t)rows[k]*1024 + cc;
        float4 t0 = *(const float4*)ut;
        float4 t1 = *(const float4*)(ut + 4);
        float uv[8] = {t0.x,t0.y,t0.z,t0.w,t1.x,t1.y,t1.z,t1.w};
        #pragma unroll
        for (int c = 0; c < 8; c++) {
            float v = acc[i][c] + uv[c] - up[c] - ub[c] + bias[cc + c];
            g_X1h[m*NHID + cc + c] = __float2bfloat16(fmaxf(v, 0.f));
        }
    }
}

__global__ __launch_bounds__(256)
void k_combine2(const float* __restrict__ bias)
{
    __shared__ float As[KK][KK];
    __shared__ float Bs[32][128];
    int b    = blockIdx.y;
    int col0 = blockIdx.x * 128;
    int t = threadIdx.x;
    int tx = t & 15, ty = t >> 4;

    const float* Ab = g_Adj + (size_t)b*KK*KK;
    for (int idx = t; idx < KK*KK; idx += 256)
        As[idx >> 6][idx & 63] = Ab[idx];

    float acc[4][8];
    #pragma unroll
    for (int i = 0; i < 4; i++)
        #pragma unroll
        for (int c = 0; c < 8; c++) acc[i][c] = 0.f;

    for (int jt = 0; jt < KK; jt += 32) {
        __syncthreads();
        #pragma unroll
        for (int i = 0; i < 4; i++) {
            int idx = t + i*256;
            int j = idx >> 5, c4 = idx & 31;
            *(float4*)&Bs[j][c4*4] =
                *(const float4*)(g_Z + (size_t)(b*KK + jt + j)*512 + 256 + col0 + c4*4);
        }
        __syncthreads();
        #pragma unroll 4
        for (int j = 0; j < 32; j++) {
            float a[4];
            #pragma unroll
            for (int i = 0; i < 4; i++) a[i] = As[ty*4 + i][jt + j];
            float4 b0 = *(const float4*)&Bs[j][tx*8];
            float4 b1 = *(const float4*)&Bs[j][tx*8 + 4];
            float bf[8] = {b0.x,b0.y,b0.z,b0.w,b1.x,b1.y,b1.z,b1.w};
            #pragma unroll
            for (int i = 0; i < 4; i++)
                #pragma unroll
                for (int c = 0; c < 8; c++)
                    acc[i][c] = fmaf(a[i], bf[c], acc[i][c]);
        }
    }
    #pragma unroll
    for (int i = 0; i < 4; i++) {
        size_t m = (size_t)(b*KK + ty*4 + i);
        #pragma unroll
        for (int c = 0; c < 8; c++) {
            int cc = col0 + tx*8 + c;
            float v = acc[i][c] + g_Z[m*512 + cc] + bias[cc];
            g_X2h[m*HH2 + cc] = __float2bfloat16(fmaxf(v, 0.f));
        }
    }
}

// classifier tail: warp per row
__global__ void k_head(const float* __restrict__ bc1,
                       const float* __restrict__ prelu_a,
                       const float* __restrict__ Wc2,
                       const float* __restrict__ bc2,
                       float* __restrict__ pred_out)
{
    int w = threadIdx.x >> 5, lane = threadIdx.x & 31;
    int m = blockIdx.x*8 + w;
    float s0 = 0.f, s1 = 0.f;
    #pragma unroll
    for (int k = 0; k < 8; k++) {
        int c = lane + k*32;
        float h = g_Hc[(size_t)m*HH2 + c] + bc1[c];
        h = (h >= 0.f) ? h : prelu_a[c]*h;
        s0 += h * Wc2[2*c];
        s1 += h * Wc2[2*c + 1];
    }
    #pragma unroll
    for (int o = 16; o > 0; o >>= 1) {
        s0 += __shfl_down_sync(0xFFFFFFFFu, s0, o);
        s1 += __shfl_down_sync(0xFFFFFFFFu, s1, o);
    }
    if (lane == 0) {
        float l0 = s0 + bc2[0];
        float l1 = s1 + bc2[1];
        float mx = fmaxf(l0, l1);
        float e0 = expf(l0 - mx), e1 = expf(l1 - mx);
        float inv = 1.0f / (e0 + e1);
        pred_out[2*m]     = e0*inv;
        pred_out[2*m + 1] = e1*inv;
    }
}

// ---------------- launch -----------------------------------------------------

extern "C" void kernel_launch(void* const* d_in, const int* in_sizes, int n_in,
                              void* d_out, int out_size)
{
    const int*   indexes  = (const int*)  d_in[0];
    const float* features = (const float*)d_in[1];
    const int*   labels   = (const int*)  d_in[2];
    const int*   knn      = (const int*)  d_in[5];
    const float* all_pred = (const float*)d_in[6];
    const float* W1  = (const float*)d_in[7];
    const float* b1  = (const float*)d_in[8];
    const float* W2  = (const float*)d_in[9];
    const float* b2  = (const float*)d_in[10];
    const float* Wc1 = (const float*)d_in[11];
    const float* bc1 = (const float*)d_in[12];
    const float* pa  = (const float*)d_in[13];
    const float* Wc2 = (const float*)d_in[14];
    const float* bc2 = (const float*)d_in[15];

    float* out = (float*)d_out;
    float* pred_out = out;
    float* simm_out = out + (size_t)MM*2;

    cudaFuncSetAttribute(k_mma_gemm, cudaFuncAttributeMaxDynamicSharedMemorySize,
                         GEMM_SMEM);

    __nv_bfloat16 *pA1h,*pW1h,*pW2h,*pWch,*pX1h,*pX2h;
    float *pU,*pZ,*pHc;
    cudaGetSymbolAddress((void**)&pA1h, g_A1h);
    cudaGetSymbolAddress((void**)&pW1h, g_W1h);
    cudaGetSymbolAddress((void**)&pW2h, g_W2h);
    cudaGetSymbolAddress((void**)&pWch, g_Wch);
    cudaGetSymbolAddress((void**)&pX1h, g_X1h);
    cudaGetSymbolAddress((void**)&pX2h, g_X2h);
    cudaGetSymbolAddress((void**)&pU,  g_U);
    cudaGetSymbolAddress((void**)&pZ,  g_Z);
    cudaGetSymbolAddress((void**)&pHc, g_Hc);

    // ---- fork S1: weight conversions (independent of data pipeline) ----
    cudaEventRecord(g_evF1, 0);
    cudaStreamWaitEvent(g_s1, g_evF1, 0);
    k_convW<<<(1024u*DD)/256, 256, 0, g_s1>>>(W1, NHID, DD, NHID, pW1h);
    k_convW<<<(512u*NHID)/256, 256, 0, g_s1>>>(W2, HH2, NHID, HH2, pW2h);
    k_convW<<<(HH2*HH2)/256, 256, 0, g_s1>>>(Wc1, HH2, HH2, HH2, pWch);
    cudaEventRecord(g_evW, g_s1);

    // ---- legacy: cluster chain ----
    k_zeroc<<<(CC + 255)/256, 256>>>();
    k_count<<<(NPTS + 255)/256, 256>>>(labels);
    k_scan<<<1, 256>>>();
    k_scatter<<<(NPTS + 255)/256, 256>>>(labels);
    k_cmean<<<CC + BB, 256>>>(features, indexes, simm_out);
    k_rowmap<<<(MM + 255)/256, 256>>>(labels, knn);

    // ---- fork S2: gram + adjacency (overlaps layer-1 GEMM) ----
    cudaEventRecord(g_evF2, 0);
    cudaStreamWaitEvent(g_s2, g_evF2, 0);
    k_gram_mma<<<BB, 256, 0, g_s2>>>();
    k_buildA<<<BB*KK, KK, 0, g_s2>>>(all_pred);
    cudaEventRecord(g_evG, g_s2);

    // ---- legacy: layer 1 GEMM (needs cmean + convW) ----
    cudaStreamWaitEvent(0, g_evW, 0);
    k_mma_gemm<<<dim3(1024/128, MU/128), 256, GEMM_SMEM>>>(DD, pA1h, pW1h, pU, 1024);

    // join gram branch, then combine + rest
    cudaStreamWaitEvent(0, g_evG, 0);
    k_combine1<<<dim3(NHID/128, BB), 256>>>(b1);
    k_mma_gemm<<<dim3(512/128, MM/128), 256, GEMM_SMEM>>>(NHID, pX1h, pW2h, pZ, 512);
    k_combine2<<<dim3(HH2/128, BB), 256>>>(b2);
    k_mma_gemm<<<dim3(HH2/128, MM/128), 256, GEMM_SMEM>>>(HH2, pX2h, pWch, pHc, 256);
    k_head<<<MM/8, 256>>>(bc1, pa, Wc2, bc2, pred_out);

    (void)in_sizes; (void)n_in; (void)out_size;
}